// round 5
// baseline (speedup 1.0000x reference)
#include <cuda_runtime.h>
#include <math.h>

#define NPKG  20000
#define NTGTN 30000
#define NE    100000
#define NTY   6
#define FIN   400
#define FD    256
#define KC    128

// ---- scratch offsets (floats) ----
#define OFF_LALL  0LL                 // 6*20000*256
#define OFF_RALL  30720000LL          // 6*30000*256
#define OFF_HPKG  76800000LL          // 20000*256
#define OFF_HTGT  81920000LL          // 30000*256
#define OFF_SPKG  89600000LL          // 20000*128
#define OFF_STGT  92160000LL          // 30000*128
#define OFF_POOL  96000000LL          // 7*128*256
#define OFF_MPKG  96229376LL
#define OFF_MT    96245760LL
#define OFF_APOOL 96262144LL          // 6*128*128
#define OFF_L2    96360448LL
#define OFF_R2    96557056LL
#define OFF_ESC   96753664LL          // max(NE*4, 6*128*128*4)
#define OFF_EMAX  97153664LL
#define OFF_EDEN  97273664LL
#define OFF_SCAL  97393664LL
#define SCRATCH_TOTAL 97393680LL

__device__ __align__(256) float g_scratch[SCRATCH_TOTAL];

__device__ __forceinline__ void atomicMaxFloat(float* addr, float val) {
    int old = __float_as_int(*addr);
    while (__int_as_float(old) < val) {
        int prev = atomicCAS((int*)addr, old, __float_as_int(val));
        if (prev == old) break;
        old = prev;
    }
}

__global__ void fill_kernel(float* __restrict__ p, float v, int n) {
    for (int i = blockIdx.x * blockDim.x + threadIdx.x; i < n; i += gridDim.x * blockDim.x)
        p[i] = v;
}

__global__ void relu_kernel(float* __restrict__ p, int n) {
    for (int i = blockIdx.x * blockDim.x + threadIdx.x; i < n; i += gridDim.x * blockDim.x)
        p[i] = fmaxf(p[i], 0.f);
}

// ================= SGEMM 128x128, BK=16, 256 thr, 8x8/thr =================
// C[M,N] = A[M,K]@B[K,N] row-major. N must be multiple of 128, K of 16.
// Batched via grid.z with strides.
__global__ __launch_bounds__(256) void sgemm128_kernel(
    const float* __restrict__ A, const float* __restrict__ B, float* __restrict__ C,
    int M, int N, int Kd, int do_relu, long long sA, long long sB, long long sC)
{
    A += (long long)blockIdx.z * sA; B += (long long)blockIdx.z * sB;
    C += (long long)blockIdx.z * sC;
    __shared__ float As[16][132];
    __shared__ float Bs[16][132];
    const int tid = threadIdx.x;
    const int tx = tid & 15, ty = tid >> 4;
    const int bm = blockIdx.y << 7, bn = blockIdx.x << 7;
    const int arow = tid >> 1, acol = (tid & 1) << 3;
    const int brow = tid >> 4, bcol = (tid & 15) << 3;
    float acc[8][8];
#pragma unroll
    for (int i = 0; i < 8; i++)
#pragma unroll
        for (int j = 0; j < 8; j++) acc[i][j] = 0.f;
    const int gr = bm + arow;
    for (int k0 = 0; k0 < Kd; k0 += 16) {
        float4 a0 = make_float4(0.f,0.f,0.f,0.f), a1 = a0;
        if (gr < M) {
            const float* ap = A + (long long)gr * Kd + k0 + acol;
            a0 = *(const float4*)ap; a1 = *(const float4*)(ap + 4);
        }
        As[acol+0][arow]=a0.x; As[acol+1][arow]=a0.y; As[acol+2][arow]=a0.z; As[acol+3][arow]=a0.w;
        As[acol+4][arow]=a1.x; As[acol+5][arow]=a1.y; As[acol+6][arow]=a1.z; As[acol+7][arow]=a1.w;
        const float* bp = B + (long long)(k0 + brow) * N + bn + bcol;
        *(float4*)&Bs[brow][bcol]     = *(const float4*)bp;
        *(float4*)&Bs[brow][bcol + 4] = *(const float4*)(bp + 4);
        __syncthreads();
#pragma unroll
        for (int k = 0; k < 16; k++) {
            float4 al = *(const float4*)&As[k][ty << 3];
            float4 ah = *(const float4*)&As[k][(ty << 3) + 4];
            float4 bl_ = *(const float4*)&Bs[k][tx << 3];
            float4 bh = *(const float4*)&Bs[k][(tx << 3) + 4];
            float ar[8] = {al.x, al.y, al.z, al.w, ah.x, ah.y, ah.z, ah.w};
            float br_[8] = {bl_.x, bl_.y, bl_.z, bl_.w, bh.x, bh.y, bh.z, bh.w};
#pragma unroll
            for (int i = 0; i < 8; i++)
#pragma unroll
                for (int j = 0; j < 8; j++) acc[i][j] = fmaf(ar[i], br_[j], acc[i][j]);
        }
        __syncthreads();
    }
#pragma unroll
    for (int i = 0; i < 8; i++) {
        int r = bm + (ty << 3) + i;
        if (r >= M) continue;
        float* cp = C + (long long)r * N + bn + (tx << 3);
#pragma unroll
        for (int h = 0; h < 2; h++) {
            float4 o = make_float4(acc[i][h*4], acc[i][h*4+1], acc[i][h*4+2], acc[i][h*4+3]);
            if (do_relu) { o.x=fmaxf(o.x,0.f); o.y=fmaxf(o.y,0.f);
                           o.z=fmaxf(o.z,0.f); o.w=fmaxf(o.w,0.f); }
            *(float4*)(cp + h*4) = o;
        }
    }
}

// ============ C[K1,K2] += A[N,K1]^T @ B[N,K2]; 128x128 tile, 8x8/thr ============
// K1,K2 multiples of 128; N split by grid.z (atomic accumulate into C).
__global__ __launch_bounds__(256) void atb128_kernel(
    const float* __restrict__ A, const float* __restrict__ B, float* __restrict__ C,
    int N, int K1, int K2)
{
    __shared__ float As[16][132];
    __shared__ float Bs[16][132];
    const int tid = threadIdx.x;
    const int tx = tid & 15, ty = tid >> 4;
    const int bk1 = blockIdx.y << 7, bk2 = blockIdx.x << 7;
    int chunk = ((N + gridDim.z - 1) / gridDim.z + 15) & ~15;
    int n0 = blockIdx.z * chunk, n1 = min(n0 + chunk, N);
    const int lrow = tid >> 4, lcol = (tid & 15) << 3;
    float acc[8][8];
#pragma unroll
    for (int i = 0; i < 8; i++)
#pragma unroll
        for (int j = 0; j < 8; j++) acc[i][j] = 0.f;
    for (int nb = n0; nb < n1; nb += 16) {
        int gn = nb + lrow;
        float4 a0 = make_float4(0.f,0.f,0.f,0.f), a1 = a0, b0 = a0, b1 = a0;
        if (gn < N) {
            const float* ap = A + (long long)gn * K1 + bk1 + lcol;
            const float* bp = B + (long long)gn * K2 + bk2 + lcol;
            a0 = *(const float4*)ap; a1 = *(const float4*)(ap + 4);
            b0 = *(const float4*)bp; b1 = *(const float4*)(bp + 4);
        }
        *(float4*)&As[lrow][lcol] = a0; *(float4*)&As[lrow][lcol+4] = a1;
        *(float4*)&Bs[lrow][lcol] = b0; *(float4*)&Bs[lrow][lcol+4] = b1;
        __syncthreads();
#pragma unroll
        for (int k = 0; k < 16; k++) {
            float4 al = *(const float4*)&As[k][ty << 3];
            float4 ah = *(const float4*)&As[k][(ty << 3) + 4];
            float4 bl_ = *(const float4*)&Bs[k][tx << 3];
            float4 bh = *(const float4*)&Bs[k][(tx << 3) + 4];
            float ar[8] = {al.x, al.y, al.z, al.w, ah.x, ah.y, ah.z, ah.w};
            float br_[8] = {bl_.x, bl_.y, bl_.z, bl_.w, bh.x, bh.y, bh.z, bh.w};
#pragma unroll
            for (int i = 0; i < 8; i++)
#pragma unroll
                for (int j = 0; j < 8; j++) acc[i][j] = fmaf(ar[i], br_[j], acc[i][j]);
        }
        __syncthreads();
    }
#pragma unroll
    for (int i = 0; i < 8; i++) {
        int r = bk1 + (ty << 3) + i;
#pragma unroll
        for (int j = 0; j < 8; j++)
            atomicAdd(&C[(long long)r * K2 + bk2 + (tx << 3) + j], acc[i][j]);
    }
}

// rows of width 128: softmax in-place + entropy accumulation (warp per row)
__global__ void softmax_ent_kernel(float* __restrict__ S, int N, float inv_n,
                                   float* __restrict__ ent_acc)
{
    int g = blockIdx.x * blockDim.x + threadIdx.x;
    int w = g >> 5, lane = g & 31;
    if (w >= N) return;
    float* row = S + (long long)w * KC;
    float v0 = row[lane], v1 = row[lane + 32], v2 = row[lane + 64], v3 = row[lane + 96];
    float m = fmaxf(fmaxf(v0, v1), fmaxf(v2, v3));
    for (int o = 16; o; o >>= 1) m = fmaxf(m, __shfl_xor_sync(~0u, m, o));
    v0 = expf(v0 - m); v1 = expf(v1 - m); v2 = expf(v2 - m); v3 = expf(v3 - m);
    float s = v0 + v1 + v2 + v3;
    for (int o = 16; o; o >>= 1) s += __shfl_xor_sync(~0u, s, o);
    float inv = 1.f / s;
    v0 *= inv; v1 *= inv; v2 *= inv; v3 *= inv;
    row[lane] = v0; row[lane + 32] = v1; row[lane + 64] = v2; row[lane + 96] = v3;
    float e = -(v0 * logf(v0 + 1e-15f) + v1 * logf(v1 + 1e-15f)
              + v2 * logf(v2 + 1e-15f) + v3 * logf(v3 + 1e-15f));
    for (int o = 16; o; o >>= 1) e += __shfl_xor_sync(~0u, e, o);
    if (lane == 0) atomicAdd(ent_acc, e * inv_n);
}

__global__ __launch_bounds__(256) void edge_score_kernel(
    const float* __restrict__ l, const float* __restrict__ r,
    const int* __restrict__ src, const int* __restrict__ tgt,
    const float* __restrict__ a1, float* __restrict__ esc, float* __restrict__ emax)
{
    __shared__ float a_s[256];
    int tid = threadIdx.x;
    a_s[tid] = a1[tid];
    __syncthreads();
    int g = blockIdx.x * blockDim.x + tid;
    int e = g >> 5, lane = g & 31;
    if (e >= NE) return;
    int t = tgt[e];
    const float* lr = l + (long long)src[e] * FD;
    const float* rr = r + (long long)t * FD;
#pragma unroll
    for (int h = 0; h < 4; h++) {
        float acc = 0.f;
#pragma unroll
        for (int q = 0; q < 2; q++) {
            int c = h * 64 + lane + q * 32;
            float v = lr[c] + rr[c];
            v = v > 0.f ? v : 0.2f * v;
            acc = fmaf(v, a_s[c], acc);
        }
        for (int o = 16; o; o >>= 1) acc += __shfl_xor_sync(~0u, acc, o);
        if (lane == 0) { esc[e * 4 + h] = acc; atomicMaxFloat(&emax[t * 4 + h], acc); }
    }
}

__global__ void edge_exp_kernel(const int* __restrict__ tgt, float* __restrict__ esc,
                                const float* __restrict__ emax, float* __restrict__ eden)
{
    int idx = blockIdx.x * blockDim.x + threadIdx.x;
    if (idx >= NE * 4) return;
    int e = idx >> 2, h = idx & 3;
    int t = tgt[e];
    float m = emax[t * 4 + h];
    if (!isfinite(m)) m = 0.f;
    float ex = expf(esc[idx] - m);
    esc[idx] = ex;
    atomicAdd(&eden[t * 4 + h], ex);
}

__global__ __launch_bounds__(256) void edge_aggr_kernel(
    const float* __restrict__ l, const int* __restrict__ src, const int* __restrict__ tgt,
    const float* __restrict__ esc, const float* __restrict__ eden, float* __restrict__ outh)
{
    int g = blockIdx.x * blockDim.x + threadIdx.x;
    int e = g >> 5, lane = g & 31;
    if (e >= NE) return;
    int s = src[e], t = tgt[e];
    float alpha[4];
#pragma unroll
    for (int h = 0; h < 4; h++)
        alpha[h] = esc[e * 4 + h] / (eden[t * 4 + h] + 1e-16f);
    const float* lr = l + (long long)s * FD;
    float* orow = outh + (long long)t * FD;
#pragma unroll
    for (int q = 0; q < 8; q++) {
        int c = lane + q * 32;
        atomicAdd(&orow[c], lr[c] * alpha[c >> 6]);
    }
}

// A_pool[t] += sum_e outer(S_pkg[src[e]], S_tgt[tgt[e]])
__global__ __launch_bounds__(256) void apool_kernel(
    const float* __restrict__ Spkg, const float* __restrict__ Stgt,
    const int* __restrict__ src, const int* __restrict__ tgt, float* __restrict__ Apool)
{
    __shared__ float ss[128], st[128];
    int tid = threadIdx.x, k = tid & 127, half = tid >> 7;
    float acc[64];
#pragma unroll
    for (int j = 0; j < 64; j++) acc[j] = 0.f;
    int per = (NE + gridDim.x - 1) / gridDim.x;
    int e0 = blockIdx.x * per, e1 = min(e0 + per, NE);
    for (int e = e0; e < e1; e++) {
        __syncthreads();
        if (half == 0) ss[k] = Spkg[(long long)src[e] * KC + k];
        else           st[k] = Stgt[(long long)tgt[e] * KC + k];
        __syncthreads();
        float a = ss[k];
        const float* p = &st[half << 6];
#pragma unroll
        for (int j = 0; j < 64; j++) acc[j] = fmaf(a, p[j], acc[j]);
    }
    float* dst = Apool + k * KC + (half << 6);
#pragma unroll
    for (int j = 0; j < 64; j++) atomicAdd(&dst[j], acc[j]);
}

__global__ void mulsum_kernel(const float* __restrict__ a, const float* __restrict__ b,
                              int n, float* __restrict__ slot)
{
    __shared__ float sred[8];
    float acc = 0.f;
    for (int i = blockIdx.x * blockDim.x + threadIdx.x; i < n; i += gridDim.x * blockDim.x)
        acc += a[i] * b[i];
    for (int o = 16; o; o >>= 1) acc += __shfl_xor_sync(~0u, acc, o);
    if ((threadIdx.x & 31) == 0) sred[threadIdx.x >> 5] = acc;
    __syncthreads();
    if (threadIdx.x == 0) {
        float t = 0.f;
        for (int i = 0; i < (int)(blockDim.x >> 5); i++) t += sred[i];
        atomicAdd(slot, t);
    }
}

__global__ __launch_bounds__(256) void edge_dot_kernel(
    const float* __restrict__ Spkg, const float* __restrict__ Stgt,
    const int* __restrict__ src, const int* __restrict__ tgt, float* __restrict__ slot)
{
    __shared__ float sred[8];
    int g = blockIdx.x * blockDim.x + threadIdx.x;
    int e = g >> 5, lane = threadIdx.x & 31;
    float acc = 0.f;
    if (e < NE) {
        const float* a = Spkg + (long long)src[e] * KC;
        const float* b = Stgt + (long long)tgt[e] * KC;
#pragma unroll
        for (int q = 0; q < 4; q++) acc += a[lane + q * 32] * b[lane + q * 32];
    }
    for (int o = 16; o; o >>= 1) acc += __shfl_xor_sync(~0u, acc, o);
    if (lane == 0) sred[threadIdx.x >> 5] = acc;
    __syncthreads();
    if (threadIdx.x == 0) {
        float t = 0.f;
        for (int i = 0; i < 8; i++) t += sred[i];
        atomicAdd(slot, t);
    }
}

__global__ void link_combine_kernel(float* __restrict__ scal) {
    float n2 = fmaxf((float)NE - 2.f * scal[2] + scal[3], 0.f) + 1e-12f;
    scal[1] += sqrtf(n2) * (1.f / ((float)NPKG * (float)NTGTN));
    scal[2] = 0.f; scal[3] = 0.f;
}

// conv2 scores: one warp per (t,i,j) pair -> e2 masked scores
__global__ __launch_bounds__(256) void attn2_score_kernel(
    const float* __restrict__ l2, const float* __restrict__ r2,
    const float* __restrict__ Apool, const float* __restrict__ a2, float* __restrict__ e2)
{
    int g = blockIdx.x * blockDim.x + threadIdx.x;
    int w = g >> 5, lane = g & 31;
    if (w >= NTY * KC * KC) return;
    int t = w >> 14, rem = w & 16383, i = rem >> 7, j = rem & 127;
    const float* li = l2 + ((long long)t * KC + i) * FD;
    const float* rj = r2 + ((long long)t * KC + j) * FD;
    const float* av = a2 + t * 256;
    float ap = Apool[(long long)t * KC * KC + i * KC + j];
#pragma unroll
    for (int h = 0; h < 4; h++) {
        float acc = 0.f;
#pragma unroll
        for (int q = 0; q < 2; q++) {
            int c = h * 64 + lane + q * 32;
            float v = li[c] + rj[c];
            v = v > 0.f ? v : 0.2f * v;
            acc = fmaf(v, av[c], acc);
        }
        for (int o = 16; o; o >>= 1) acc += __shfl_xor_sync(~0u, acc, o);
        if (lane == 0) e2[(long long)w * 4 + h] = (ap > 0.f) ? acc : -1e9f;
    }
}

// softmax over i (source clusters) for fixed (t,j,h)
__global__ __launch_bounds__(128) void attn2_softmax_kernel(
    const float* __restrict__ e2, float* __restrict__ out_attn)
{
    int j = blockIdx.x, t = blockIdx.y, i = threadIdx.x;
    int lane = i & 31, wid = i >> 5;
    __shared__ float wred[4][4];
    long long base = (((long long)t * KC + i) * KC + j) * 4;
    float e[4], m[4], ex[4];
#pragma unroll
    for (int h = 0; h < 4; h++) e[h] = e2[base + h];
#pragma unroll
    for (int h = 0; h < 4; h++) {
        float x = e[h];
        for (int o = 16; o; o >>= 1) x = fmaxf(x, __shfl_xor_sync(~0u, x, o));
        if (lane == 0) wred[wid][h] = x;
    }
    __syncthreads();
#pragma unroll
    for (int h = 0; h < 4; h++)
        m[h] = fmaxf(fmaxf(wred[0][h], wred[1][h]), fmaxf(wred[2][h], wred[3][h]));
    __syncthreads();
#pragma unroll
    for (int h = 0; h < 4; h++) {
        ex[h] = expf(e[h] - m[h]);
        float x = ex[h];
        for (int o = 16; o; o >>= 1) x += __shfl_xor_sync(~0u, x, o);
        if (lane == 0) wred[wid][h] = x;
    }
    __syncthreads();
#pragma unroll
    for (int h = 0; h < 4; h++) {
        float sm = wred[0][h] + wred[1][h] + wred[2][h] + wred[3][h];
        out_attn[base + h] = ex[h] / sm;
    }
}

__global__ void cls_kernel(const float* __restrict__ pool, const float* __restrict__ Wcls,
                           const float* __restrict__ bcls, float* __restrict__ out)
{
    int g = blockIdx.x * blockDim.x + threadIdx.x;
    int w = g >> 5, lane = g & 31;
    if (w >= (NTY + 1) * KC) return;
    const float* row = pool + (long long)w * FD;
    float acc = 0.f;
#pragma unroll
    for (int q = 0; q < 8; q++) acc += row[lane + q * 32] * Wcls[lane + q * 32];
    for (int o = 16; o; o >>= 1) acc += __shfl_xor_sync(~0u, acc, o);
    if (lane == 0) out[w] = 1.f / (1.f + expf(-(acc + bcls[0])));
}

__global__ void finalize_kernel(const float* __restrict__ scal, float* __restrict__ out) {
    out[(NTY + 1) * KC] = scal[0] + scal[1];
}

extern "C" void kernel_launch(void* const* d_in, const int* in_sizes, int n_in,
                              void* d_out, int out_size)
{
    (void)in_sizes; (void)n_in; (void)out_size;
    const float* x_pkg   = (const float*)d_in[0];
    const float* x_tgt   = (const float*)d_in[1];
    const int*   src_idx = (const int*)d_in[2];
    const int*   tgt_idx = (const int*)d_in[3];
    const float* W1s     = (const float*)d_in[4];
    const float* W1t     = (const float*)d_in[5];
    const float* a1      = (const float*)d_in[6];
    const float* Wpkg    = (const float*)d_in[7];
    const float* Wassign = (const float*)d_in[8];
    const float* W2s     = (const float*)d_in[9];
    const float* W2t     = (const float*)d_in[10];
    const float* a2      = (const float*)d_in[11];
    const float* Wcls    = (const float*)d_in[12];
    const float* bcls    = (const float*)d_in[13];
    float* out = (float*)d_out;

    void* sp = nullptr;
    cudaGetSymbolAddress(&sp, g_scratch);
    float* S = (float*)sp;
    float* l_all = S + OFF_LALL;
    float* r_all = S + OFF_RALL;
    float* hpkg  = S + OFF_HPKG;
    float* htgt  = S + OFF_HTGT;
    float* Spkg  = S + OFF_SPKG;
    float* Stgt  = S + OFF_STGT;
    float* pool  = S + OFF_POOL;
    float* Mpkg  = S + OFF_MPKG;
    float* Mt    = S + OFF_MT;
    float* Apool = S + OFF_APOOL;
    float* l2    = S + OFF_L2;
    float* r2    = S + OFF_R2;
    float* esc   = S + OFF_ESC;
    float* emax  = S + OFF_EMAX;
    float* eden  = S + OFF_EDEN;
    float* scal  = S + OFF_SCAL;

    fill_kernel<<<1, 32>>>(scal, 0.f, 16);
    fill_kernel<<<512, 256>>>(pool, 0.f, 7 * KC * FD);
    fill_kernel<<<64, 256>>>(Mpkg, 0.f, KC * KC);
    fill_kernel<<<256, 256>>>(Apool, 0.f, NTY * KC * KC);

    // --- batched conv1 projections for all 6 types ---
    sgemm128_kernel<<<dim3(FD / 128, (NPKG + 127) / 128, NTY), 256>>>(
        x_pkg, W1s, l_all, NPKG, FD, FIN, 0,
        0LL, (long long)FIN * FD, (long long)NPKG * FD);
    sgemm128_kernel<<<dim3(FD / 128, (NTGTN + 127) / 128, NTY), 256>>>(
        x_tgt, W1t, r_all, NTGTN, FD, FIN, 0,
        (long long)NTGTN * FIN, (long long)FIN * FD, (long long)NTGTN * FD);

    // --- pkg side: h_pkg, S_pkg, p_pkg, M_pkg ---
    sgemm128_kernel<<<dim3(FD / 128, (NPKG + 127) / 128), 256>>>(
        x_pkg, Wpkg, hpkg, NPKG, FD, FIN, 1, 0, 0, 0);
    sgemm128_kernel<<<dim3(KC / 128, (NPKG + 127) / 128), 256>>>(
        hpkg, Wassign, Spkg, NPKG, KC, FD, 0, 0, 0, 0);
    softmax_ent_kernel<<<(NPKG + 7) / 8, 256>>>(Spkg, NPKG, 1.0f / NPKG, scal);
    atb128_kernel<<<dim3(FD / 128, KC / 128, 64), 256>>>(Spkg, hpkg, pool, NPKG, KC, FD);
    atb128_kernel<<<dim3(KC / 128, KC / 128, 64), 256>>>(Spkg, Spkg, Mpkg, NPKG, KC, KC);

    for (int t = 0; t < NTY; t++) {
        const float* bl  = l_all + (long long)t * NPKG * FD;
        const float* brr = r_all + (long long)t * NTGTN * FD;
        const int* se = src_idx + (long long)t * NE;
        const int* te = tgt_idx + (long long)t * NE;

        fill_kernel<<<128, 256>>>(emax, -INFINITY, NTGTN * 4);
        fill_kernel<<<128, 256>>>(eden, 0.f, NTGTN * 4);
        fill_kernel<<<1024, 256>>>(htgt, 0.f, NTGTN * FD);

        edge_score_kernel<<<NE * 32 / 256, 256>>>(bl, brr, se, te, a1 + t * 256, esc, emax);
        edge_exp_kernel<<<(NE * 4 + 255) / 256, 256>>>(te, esc, emax, eden);
        edge_aggr_kernel<<<NE * 32 / 256, 256>>>(bl, se, te, esc, eden, htgt);
        relu_kernel<<<1024, 256>>>(htgt, NTGTN * FD);

        sgemm128_kernel<<<dim3(KC / 128, (NTGTN + 127) / 128), 256>>>(
            htgt, Wassign + (long long)(t + 1) * FD * KC, Stgt, NTGTN, KC, FD, 0, 0, 0, 0);
        softmax_ent_kernel<<<(NTGTN + 7) / 8, 256>>>(Stgt, NTGTN, 1.0f / NTGTN, scal);

        atb128_kernel<<<dim3(FD / 128, KC / 128, 64), 256>>>(
            Stgt, htgt, pool + (long long)(t + 1) * KC * FD, NTGTN, KC, FD);
        fill_kernel<<<64, 256>>>(Mt, 0.f, KC * KC);
        atb128_kernel<<<dim3(KC / 128, KC / 128, 64), 256>>>(Stgt, Stgt, Mt, NTGTN, KC, KC);

        edge_dot_kernel<<<NE * 32 / 256, 256>>>(Spkg, Stgt, se, te, scal + 2);
        mulsum_kernel<<<8, 256>>>(Mpkg, Mt, KC * KC, scal + 3);
        link_combine_kernel<<<1, 1>>>(scal);

        apool_kernel<<<896, 256>>>(Spkg, Stgt, se, te, Apool + (long long)t * KC * KC);
    }

    // conv2 projections (batched over 6 types)
    sgemm128_kernel<<<dim3(FD / 128, 1, NTY), 256>>>(
        pool, W2s, l2, KC, FD, FD, 0, 0, (long long)FD * FD, (long long)KC * FD);
    sgemm128_kernel<<<dim3(FD / 128, 1, NTY), 256>>>(
        pool + (long long)KC * FD, W2t, r2, KC, FD, FD, 0,
        (long long)KC * FD, (long long)FD * FD, (long long)KC * FD);

    attn2_score_kernel<<<NTY * KC * KC * 32 / 256, 256>>>(l2, r2, Apool, a2, esc);
    attn2_softmax_kernel<<<dim3(KC, NTY), 128>>>(esc, out + (NTY + 1) * KC + 1);

    cls_kernel<<<(NTY + 1) * KC * 32 / 256, 256>>>(pool, Wcls, bcls, out);
    finalize_kernel<<<1, 1>>>(scal, out);
}

// round 6
// speedup vs baseline: 1.1621x; 1.1621x over previous
#include <cuda_runtime.h>
#include <cuda_bf16.h>
#include <math.h>

#define NPKG  20000
#define NTGTN 30000
#define NE    100000
#define NTY   6
#define FIN   400
#define FD    256
#define KC    128
#define KP1   1216   // padded 3*400
#define KP2   768    // 3*256

// ---------------- byte-offset arena ----------------
#define O_LALL  0LL
#define O_RALL  122880000LL
#define O_HPKG  307200000LL
#define O_HTGT  327680000LL
#define O_SPKG  358400000LL
#define O_STGT  368640000LL
#define O_POOL  384000000LL
#define O_MPKG  384917504LL
#define O_MT    384983040LL
#define O_APOOL 385048576LL
#define O_L2    385441792LL
#define O_R2    386228224LL
#define O_ESC   387014656LL
#define O_EMAX  388614656LL
#define O_EDEN  389094656LL
#define O_SCAL  389574656LL
#define O_XPKG3 389574912LL
#define O_XTGT3 438214912LL
#define O_W1S3  875974912LL
#define O_W1T3  879710464LL
#define O_WPKG3 883446016LL
#define O_HPKG3 884068608LL
#define O_HTGT3 914788608LL
#define O_WAS3  960868608LL
#define ARENA_BYTES 962244864LL

__device__ __align__(256) char g_arena[ARENA_BYTES];

typedef __nv_bfloat16 bf16;

__device__ __forceinline__ void atomicMaxFloat(float* addr, float val) {
    int old = __float_as_int(*addr);
    while (__int_as_float(old) < val) {
        int prev = atomicCAS((int*)addr, old, __float_as_int(val));
        if (prev == old) break;
        old = prev;
    }
}

__global__ void fill_kernel(float* __restrict__ p, float v, int n) {
    for (int i = blockIdx.x * blockDim.x + threadIdx.x; i < n; i += gridDim.x * blockDim.x)
        p[i] = v;
}

__global__ void relu_kernel(float* __restrict__ p, int n) {
    for (int i = blockIdx.x * blockDim.x + threadIdx.x; i < n; i += gridDim.x * blockDim.x)
        p[i] = fmaxf(p[i], 0.f);
}

// ---------- fp32 -> split-bf16 triplet conversions ----------
// A-side: X[rows][K] -> Y[rows][Kp] with Y[r][3k+0]=hi, [3k+1]=hi, [3k+2]=lo
__global__ void cvtA_kernel(const float* __restrict__ X, bf16* __restrict__ Y,
                            int K, int Kp, long long total)
{
    for (long long i = blockIdx.x * (long long)blockDim.x + threadIdx.x; i < total;
         i += (long long)gridDim.x * blockDim.x) {
        long long r = i / K;
        int k = (int)(i - r * K);
        float x = X[i];
        bf16 h = __float2bfloat16(x);
        bf16 lo = __float2bfloat16(x - __bfloat162float(h));
        bf16* row = Y + r * Kp + 3 * k;
        row[0] = h; row[1] = h; row[2] = lo;
    }
}
__global__ void padA_kernel(bf16* __restrict__ Y, long long rows, int K3, int Kp) {
    int pw = Kp - K3;
    long long total = rows * pw;
    for (long long i = blockIdx.x * (long long)blockDim.x + threadIdx.x; i < total;
         i += (long long)gridDim.x * blockDim.x) {
        long long r = i / pw;
        Y[r * Kp + K3 + (int)(i - r * pw)] = __float2bfloat16(0.f);
    }
}
// B-side: X[nb][K][N] -> Y[nb][Kp][N] with [3k]=hi, [3k+1]=lo, [3k+2]=hi
__global__ void cvtB_kernel(const float* __restrict__ X, bf16* __restrict__ Y,
                            int K, int N, int Kp, long long total)
{
    long long KN = (long long)K * N;
    for (long long i = blockIdx.x * (long long)blockDim.x + threadIdx.x; i < total;
         i += (long long)gridDim.x * blockDim.x) {
        long long b = i / KN;
        long long rem = i - b * KN;
        int k = (int)(rem / N), n = (int)(rem - (long long)k * N);
        float x = X[i];
        bf16 h = __float2bfloat16(x);
        bf16 lo = __float2bfloat16(x - __bfloat162float(h));
        bf16* base = Y + (b * Kp + 3 * k) * N + n;
        base[0] = h; base[N] = lo; base[2 * N] = h;
    }
}
__global__ void padB_kernel(bf16* __restrict__ Y, int nb, int K3, int Kp, int N) {
    long long total = (long long)nb * (Kp - K3) * N;
    int pw = Kp - K3;
    for (long long i = blockIdx.x * (long long)blockDim.x + threadIdx.x; i < total;
         i += (long long)gridDim.x * blockDim.x) {
        long long b = i / ((long long)pw * N);
        long long rem = i - b * (long long)pw * N;
        int k = (int)(rem / N), n = (int)(rem % N);
        Y[(b * Kp + K3 + k) * N + n] = __float2bfloat16(0.f);
    }
}

// ---------- bf16 tensor-core GEMM: C[M,N] = A[M,Kp] @ B[Kp,N] ----------
// CTA 128x128, 8 warps (2m x 4n), warp 64x32, mma m16n8k16. Batched grid.z.
__global__ __launch_bounds__(256) void bmma_kernel(
    const bf16* __restrict__ A, const bf16* __restrict__ B, float* __restrict__ C,
    int M, int N, int Kp, int do_relu, long long sA, long long sB, long long sC)
{
    A += (long long)blockIdx.z * sA;
    B += (long long)blockIdx.z * sB;
    C += (long long)blockIdx.z * sC;
    __shared__ bf16 As[128 * 40];    // row stride 40 (32 + 8 pad)
    __shared__ bf16 Bs[32 * 136];    // row stride 136 (128 + 8 pad)
    const int tid = threadIdx.x;
    const int w = tid >> 5, l = tid & 31;
    const int wm = w & 1, wn = w >> 1;
    const int bm = blockIdx.y << 7, bn = blockIdx.x << 7;

    float acc[4][4][4];
#pragma unroll
    for (int a = 0; a < 4; a++)
#pragma unroll
        for (int b = 0; b < 4; b++)
#pragma unroll
            for (int c = 0; c < 4; c++) acc[a][b][c] = 0.f;

    unsigned a_addr[4], b_addr[4];
#pragma unroll
    for (int mt = 0; mt < 4; mt++) {
        int row = wm * 64 + mt * 16 + (l & 7) + ((l >> 3) & 1) * 8;
        int col = (l >> 4) << 3;
        a_addr[mt] = (unsigned)__cvta_generic_to_shared(&As[row * 40 + col]);
    }
#pragma unroll
    for (int nt = 0; nt < 4; nt++) {
        int krow = l & 15;
        int col = wn * 32 + nt * 8;
        b_addr[nt] = (unsigned)__cvta_generic_to_shared(&Bs[krow * 136 + col]);
    }

    const int a_row = tid >> 1, a_grp = (tid & 1) << 3;      // +256: rows 128.. handled by slot
    const int b_k = tid >> 4, b_grp = (tid & 15) << 3;

    for (int k0 = 0; k0 < Kp; k0 += 32) {
        // load A chunk: 512 slots of 8 bf16
#pragma unroll
        for (int it = 0; it < 2; it++) {
            int slot = tid + it * 256;
            int row = slot >> 2, grp = (slot & 3) << 3;
            uint4 v = make_uint4(0u, 0u, 0u, 0u);
            if (bm + row < M)
                v = *(const uint4*)(A + (long long)(bm + row) * Kp + k0 + grp);
            *(uint4*)&As[row * 40 + grp] = v;
        }
        // load B chunk
#pragma unroll
        for (int it = 0; it < 2; it++) {
            int slot = tid + it * 256;
            int kk = slot >> 4, grp = (slot & 15) << 3;
            *(uint4*)&Bs[kk * 136 + grp] =
                *(const uint4*)(B + (long long)(k0 + kk) * N + bn + grp);
        }
        __syncthreads();
#pragma unroll
        for (int s = 0; s < 2; s++) {
            unsigned af[4][4], bfr[4][2];
#pragma unroll
            for (int mt = 0; mt < 4; mt++) {
                asm volatile(
                    "ldmatrix.sync.aligned.m8n8.x4.shared.b16 {%0,%1,%2,%3}, [%4];"
                    : "=r"(af[mt][0]), "=r"(af[mt][1]), "=r"(af[mt][2]), "=r"(af[mt][3])
                    : "r"(a_addr[mt] + s * 32));
            }
#pragma unroll
            for (int nt = 0; nt < 4; nt++) {
                asm volatile(
                    "ldmatrix.sync.aligned.m8n8.x2.trans.shared.b16 {%0,%1}, [%2];"
                    : "=r"(bfr[nt][0]), "=r"(bfr[nt][1])
                    : "r"(b_addr[nt] + s * 4352));
            }
#pragma unroll
            for (int mt = 0; mt < 4; mt++)
#pragma unroll
                for (int nt = 0; nt < 4; nt++) {
                    asm volatile(
                        "mma.sync.aligned.m16n8k16.row.col.f32.bf16.bf16.f32 "
                        "{%0,%1,%2,%3}, {%4,%5,%6,%7}, {%8,%9}, {%0,%1,%2,%3};"
                        : "+f"(acc[mt][nt][0]), "+f"(acc[mt][nt][1]),
                          "+f"(acc[mt][nt][2]), "+f"(acc[mt][nt][3])
                        : "r"(af[mt][0]), "r"(af[mt][1]), "r"(af[mt][2]), "r"(af[mt][3]),
                          "r"(bfr[nt][0]), "r"(bfr[nt][1]));
                }
        }
        __syncthreads();
    }
    // store
#pragma unroll
    for (int mt = 0; mt < 4; mt++) {
        int rr = bm + wm * 64 + mt * 16 + (l >> 2);
#pragma unroll
        for (int nt = 0; nt < 4; nt++) {
            int cc = bn + wn * 32 + nt * 8 + ((l & 3) << 1);
            float c0 = acc[mt][nt][0], c1 = acc[mt][nt][1];
            float c2 = acc[mt][nt][2], c3 = acc[mt][nt][3];
            if (do_relu) {
                c0 = fmaxf(c0, 0.f); c1 = fmaxf(c1, 0.f);
                c2 = fmaxf(c2, 0.f); c3 = fmaxf(c3, 0.f);
            }
            if (rr < M) {
                C[(long long)rr * N + cc] = c0;
                C[(long long)rr * N + cc + 1] = c1;
            }
            if (rr + 8 < M) {
                C[(long long)(rr + 8) * N + cc] = c2;
                C[(long long)(rr + 8) * N + cc + 1] = c3;
            }
        }
    }
}

// ---------- fp32 SGEMM (small conv2 GEMMs only) ----------
__global__ __launch_bounds__(256) void sgemm_kernel(
    const float* __restrict__ A, const float* __restrict__ B, float* __restrict__ C,
    int M, int N, int Kd, long long sA, long long sB, long long sC)
{
    A += (long long)blockIdx.z * sA; B += (long long)blockIdx.z * sB;
    C += (long long)blockIdx.z * sC;
    __shared__ float As[16][68], Bs[16][68];
    const int tid = threadIdx.x, tx = tid & 15, ty = tid >> 4;
    const int bm = blockIdx.y << 6, bn = blockIdx.x << 6;
    const int arow = tid >> 2, acol = (tid & 3) << 2;
    const int brow = tid >> 4, bcol = (tid & 15) << 2;
    float acc[4][4];
#pragma unroll
    for (int i = 0; i < 4; i++)
#pragma unroll
        for (int j = 0; j < 4; j++) acc[i][j] = 0.f;
    const int gr = bm + arow;
    for (int k0 = 0; k0 < Kd; k0 += 16) {
        float4 av = make_float4(0.f, 0.f, 0.f, 0.f);
        if (gr < M) av = *(const float4*)(A + (long long)gr * Kd + k0 + acol);
        As[acol][arow] = av.x; As[acol + 1][arow] = av.y;
        As[acol + 2][arow] = av.z; As[acol + 3][arow] = av.w;
        *(float4*)&Bs[brow][bcol] = *(const float4*)(B + (long long)(k0 + brow) * N + bn + bcol);
        __syncthreads();
#pragma unroll
        for (int k = 0; k < 16; k++) {
            float4 a4 = *(const float4*)&As[k][ty << 2];
            float4 b4 = *(const float4*)&Bs[k][tx << 2];
            float ar[4] = {a4.x, a4.y, a4.z, a4.w};
            float br_[4] = {b4.x, b4.y, b4.z, b4.w};
#pragma unroll
            for (int i = 0; i < 4; i++)
#pragma unroll
                for (int j = 0; j < 4; j++) acc[i][j] = fmaf(ar[i], br_[j], acc[i][j]);
        }
        __syncthreads();
    }
#pragma unroll
    for (int i = 0; i < 4; i++) {
        int r = bm + (ty << 2) + i;
        if (r >= M) continue;
        *(float4*)(C + (long long)r * N + bn + (tx << 2)) =
            make_float4(acc[i][0], acc[i][1], acc[i][2], acc[i][3]);
    }
}

// ---------- C[K1,K2] += A[N,K1]^T @ B[N,K2]; fp32, N split by grid.z ----------
__global__ __launch_bounds__(256) void atb_kernel(
    const float* __restrict__ A, const float* __restrict__ B, float* __restrict__ C,
    int N, int K1, int K2)
{
    __shared__ float As[16][68], Bs[16][68];
    const int tid = threadIdx.x, tx = tid & 15, ty = tid >> 4;
    const int bk1 = blockIdx.y << 6, bk2 = blockIdx.x << 6;
    int chunk = ((N + gridDim.z - 1) / gridDim.z + 15) & ~15;
    int n0 = blockIdx.z * chunk, n1 = min(n0 + chunk, N);
    const int lrow = tid >> 4, lcol = (tid & 15) << 2;
    float acc[4][4];
#pragma unroll
    for (int i = 0; i < 4; i++)
#pragma unroll
        for (int j = 0; j < 4; j++) acc[i][j] = 0.f;
    for (int nb = n0; nb < n1; nb += 16) {
        int gn = nb + lrow;
        float4 a = make_float4(0.f, 0.f, 0.f, 0.f), b = a;
        if (gn < N) {
            a = *(const float4*)(A + (long long)gn * K1 + bk1 + lcol);
            b = *(const float4*)(B + (long long)gn * K2 + bk2 + lcol);
        }
        *(float4*)&As[lrow][lcol] = a;
        *(float4*)&Bs[lrow][lcol] = b;
        __syncthreads();
#pragma unroll
        for (int k = 0; k < 16; k++) {
            float4 a4 = *(const float4*)&As[k][ty << 2];
            float4 b4 = *(const float4*)&Bs[k][tx << 2];
            float ar[4] = {a4.x, a4.y, a4.z, a4.w};
            float br_[4] = {b4.x, b4.y, b4.z, b4.w};
#pragma unroll
            for (int i = 0; i < 4; i++)
#pragma unroll
                for (int j = 0; j < 4; j++) acc[i][j] = fmaf(ar[i], br_[j], acc[i][j]);
        }
        __syncthreads();
    }
#pragma unroll
    for (int i = 0; i < 4; i++) {
        int r = bk1 + (ty << 2) + i;
#pragma unroll
        for (int j = 0; j < 4; j++)
            atomicAdd(&C[(long long)r * K2 + bk2 + (tx << 2) + j], acc[i][j]);
    }
}

__global__ void softmax_ent_kernel(float* __restrict__ S, int N, float inv_n,
                                   float* __restrict__ ent_acc)
{
    int g = blockIdx.x * blockDim.x + threadIdx.x;
    int w = g >> 5, lane = g & 31;
    if (w >= N) return;
    float* row = S + (long long)w * KC;
    float v0 = row[lane], v1 = row[lane + 32], v2 = row[lane + 64], v3 = row[lane + 96];
    float m = fmaxf(fmaxf(v0, v1), fmaxf(v2, v3));
    for (int o = 16; o; o >>= 1) m = fmaxf(m, __shfl_xor_sync(~0u, m, o));
    v0 = expf(v0 - m); v1 = expf(v1 - m); v2 = expf(v2 - m); v3 = expf(v3 - m);
    float s = v0 + v1 + v2 + v3;
    for (int o = 16; o; o >>= 1) s += __shfl_xor_sync(~0u, s, o);
    float inv = 1.f / s;
    v0 *= inv; v1 *= inv; v2 *= inv; v3 *= inv;
    row[lane] = v0; row[lane + 32] = v1; row[lane + 64] = v2; row[lane + 96] = v3;
    float e = -(v0 * logf(v0 + 1e-15f) + v1 * logf(v1 + 1e-15f)
              + v2 * logf(v2 + 1e-15f) + v3 * logf(v3 + 1e-15f));
    for (int o = 16; o; o >>= 1) e += __shfl_xor_sync(~0u, e, o);
    if (lane == 0) atomicAdd(ent_acc, e * inv_n);
}

__global__ __launch_bounds__(256) void edge_score_kernel(
    const float* __restrict__ l, const float* __restrict__ r,
    const int* __restrict__ src, const int* __restrict__ tgt,
    const float* __restrict__ a1, float* __restrict__ esc, float* __restrict__ emax)
{
    __shared__ float a_s[256];
    int tid = threadIdx.x;
    a_s[tid] = a1[tid];
    __syncthreads();
    int g = blockIdx.x * blockDim.x + tid;
    int e = g >> 5, lane = g & 31;
    if (e >= NE) return;
    int t = tgt[e];
    const float* lr = l + (long long)src[e] * FD;
    const float* rr = r + (long long)t * FD;
#pragma unroll
    for (int h = 0; h < 4; h++) {
        float acc = 0.f;
#pragma unroll
        for (int q = 0; q < 2; q++) {
            int c = h * 64 + lane + q * 32;
            float v = lr[c] + rr[c];
            v = v > 0.f ? v : 0.2f * v;
            acc = fmaf(v, a_s[c], acc);
        }
        for (int o = 16; o; o >>= 1) acc += __shfl_xor_sync(~0u, acc, o);
        if (lane == 0) { esc[e * 4 + h] = acc; atomicMaxFloat(&emax[t * 4 + h], acc); }
    }
}

__global__ void edge_exp_kernel(const int* __restrict__ tgt, float* __restrict__ esc,
                                const float* __restrict__ emax, float* __restrict__ eden)
{
    int idx = blockIdx.x * blockDim.x + threadIdx.x;
    if (idx >= NE * 4) return;
    int e = idx >> 2, h = idx & 3;
    int t = tgt[e];
    float m = emax[t * 4 + h];
    if (!isfinite(m)) m = 0.f;
    float ex = expf(esc[idx] - m);
    esc[idx] = ex;
    atomicAdd(&eden[t * 4 + h], ex);
}

__global__ __launch_bounds__(256) void edge_aggr_kernel(
    const float* __restrict__ l, const int* __restrict__ src, const int* __restrict__ tgt,
    const float* __restrict__ esc, const float* __restrict__ eden, float* __restrict__ outh)
{
    int g = blockIdx.x * blockDim.x + threadIdx.x;
    int e = g >> 5, lane = g & 31;
    if (e >= NE) return;
    int s = src[e], t = tgt[e];
    float alpha[4];
#pragma unroll
    for (int h = 0; h < 4; h++)
        alpha[h] = esc[e * 4 + h] / (eden[t * 4 + h] + 1e-16f);
    const float* lr = l + (long long)s * FD;
    float* orow = outh + (long long)t * FD;
#pragma unroll
    for (int q = 0; q < 8; q++) {
        int c = lane + q * 32;
        atomicAdd(&orow[c], lr[c] * alpha[c >> 6]);
    }
}

__global__ __launch_bounds__(256) void apool_kernel(
    const float* __restrict__ Spkg, const float* __restrict__ Stgt,
    const int* __restrict__ src, const int* __restrict__ tgt, float* __restrict__ Apool)
{
    __shared__ float ss[128], st[128];
    int tid = threadIdx.x, k = tid & 127, half = tid >> 7;
    float acc[64];
#pragma unroll
    for (int j = 0; j < 64; j++) acc[j] = 0.f;
    int per = (NE + gridDim.x - 1) / gridDim.x;
    int e0 = blockIdx.x * per, e1 = min(e0 + per, NE);
    for (int e = e0; e < e1; e++) {
        __syncthreads();
        if (half == 0) ss[k] = Spkg[(long long)src[e] * KC + k];
        else           st[k] = Stgt[(long long)tgt[e] * KC + k];
        __syncthreads();
        float a = ss[k];
        const float* p = &st[half << 6];
#pragma unroll
        for (int j = 0; j < 64; j++) acc[j] = fmaf(a, p[j], acc[j]);
    }
    float* dst = Apool + k * KC + (half << 6);
#pragma unroll
    for (int j = 0; j < 64; j++) atomicAdd(&dst[j], acc[j]);
}

__global__ void mulsum_kernel(const float* __restrict__ a, const float* __restrict__ b,
                              int n, float* __restrict__ slot)
{
    __shared__ float sred[8];
    float acc = 0.f;
    for (int i = blockIdx.x * blockDim.x + threadIdx.x; i < n; i += gridDim.x * blockDim.x)
        acc += a[i] * b[i];
    for (int o = 16; o; o >>= 1) acc += __shfl_xor_sync(~0u, acc, o);
    if ((threadIdx.x & 31) == 0) sred[threadIdx.x >> 5] = acc;
    __syncthreads();
    if (threadIdx.x == 0) {
        float t = 0.f;
        for (int i = 0; i < (int)(blockDim.x >> 5); i++) t += sred[i];
        atomicAdd(slot, t);
    }
}

__global__ __launch_bounds__(256) void edge_dot_kernel(
    const float* __restrict__ Spkg, const float* __restrict__ Stgt,
    const int* __restrict__ src, const int* __restrict__ tgt, float* __restrict__ slot)
{
    __shared__ float sred[8];
    int g = blockIdx.x * blockDim.x + threadIdx.x;
    int e = g >> 5, lane = threadIdx.x & 31;
    float acc = 0.f;
    if (e < NE) {
        const float* a = Spkg + (long long)src[e] * KC;
        const float* b = Stgt + (long long)tgt[e] * KC;
#pragma unroll
        for (int q = 0; q < 4; q++) acc += a[lane + q * 32] * b[lane + q * 32];
    }
    for (int o = 16; o; o >>= 1) acc += __shfl_xor_sync(~0u, acc, o);
    if (lane == 0) sred[threadIdx.x >> 5] = acc;
    __syncthreads();
    if (threadIdx.x == 0) {
        float t = 0.f;
        for (int i = 0; i < 8; i++) t += sred[i];
        atomicAdd(slot, t);
    }
}

__global__ void link_combine_kernel(float* __restrict__ scal) {
    float n2 = fmaxf((float)NE - 2.f * scal[2] + scal[3], 0.f) + 1e-12f;
    scal[1] += sqrtf(n2) * (1.f / ((float)NPKG * (float)NTGTN));
    scal[2] = 0.f; scal[3] = 0.f;
}

__global__ __launch_bounds__(256) void attn2_score_kernel(
    const float* __restrict__ l2, const float* __restrict__ r2,
    const float* __restrict__ Apool, const float* __restrict__ a2, float* __restrict__ e2)
{
    int g = blockIdx.x * blockDim.x + threadIdx.x;
    int w = g >> 5, lane = g & 31;
    if (w >= NTY * KC * KC) return;
    int t = w >> 14, rem = w & 16383, i = rem >> 7, j = rem & 127;
    const float* li = l2 + ((long long)t * KC + i) * FD;
    const float* rj = r2 + ((long long)t * KC + j) * FD;
    const float* av = a2 + t * 256;
    float ap = Apool[(long long)t * KC * KC + i * KC + j];
#pragma unroll
    for (int h = 0; h < 4; h++) {
        float acc = 0.f;
#pragma unroll
        for (int q = 0; q < 2; q++) {
            int c = h * 64 + lane + q * 32;
            float v = li[c] + rj[c];
            v = v > 0.f ? v : 0.2f * v;
            acc = fmaf(v, av[c], acc);
        }
        for (int o = 16; o; o >>= 1) acc += __shfl_xor_sync(~0u, acc, o);
        if (lane == 0) e2[(long long)w * 4 + h] = (ap > 0.f) ? acc : -1e9f;
    }
}

__global__ __launch_bounds__(128) void attn2_softmax_kernel(
    const float* __restrict__ e2, float* __restrict__ out_attn)
{
    int j = blockIdx.x, t = blockIdx.y, i = threadIdx.x;
    int lane = i & 31, wid = i >> 5;
    __shared__ float wred[4][4];
    long long base = (((long long)t * KC + i) * KC + j) * 4;
    float e[4], m[4], ex[4];
#pragma unroll
    for (int h = 0; h < 4; h++) e[h] = e2[base + h];
#pragma unroll
    for (int h = 0; h < 4; h++) {
        float x = e[h];
        for (int o = 16; o; o >>= 1) x = fmaxf(x, __shfl_xor_sync(~0u, x, o));
        if (lane == 0) wred[wid][h] = x;
    }
    __syncthreads();
#pragma unroll
    for (int h = 0; h < 4; h++)
        m[h] = fmaxf(fmaxf(wred[0][h], wred[1][h]), fmaxf(wred[2][h], wred[3][h]));
    __syncthreads();
#pragma unroll
    for (int h = 0; h < 4; h++) {
        ex[h] = expf(e[h] - m[h]);
        float x = ex[h];
        for (int o = 16; o; o >>= 1) x += __shfl_xor_sync(~0u, x, o);
        if (lane == 0) wred[wid][h] = x;
    }
    __syncthreads();
#pragma unroll
    for (int h = 0; h < 4; h++) {
        float sm = wred[0][h] + wred[1][h] + wred[2][h] + wred[3][h];
        out_attn[base + h] = ex[h] / sm;
    }
}

__global__ void cls_kernel(const float* __restrict__ pool, const float* __restrict__ Wcls,
                           const float* __restrict__ bcls, float* __restrict__ out)
{
    int g = blockIdx.x * blockDim.x + threadIdx.x;
    int w = g >> 5, lane = g & 31;
    if (w >= (NTY + 1) * KC) return;
    const float* row = pool + (long long)w * FD;
    float acc = 0.f;
#pragma unroll
    for (int q = 0; q < 8; q++) acc += row[lane + q * 32] * Wcls[lane + q * 32];
    for (int o = 16; o; o >>= 1) acc += __shfl_xor_sync(~0u, acc, o);
    if (lane == 0) out[w] = 1.f / (1.f + expf(-(acc + bcls[0])));
}

__global__ void finalize_kernel(const float* __restrict__ scal, float* __restrict__ out) {
    out[(NTY + 1) * KC] = scal[0] + scal[1];
}

extern "C" void kernel_launch(void* const* d_in, const int* in_sizes, int n_in,
                              void* d_out, int out_size)
{
    (void)in_sizes; (void)n_in; (void)out_size;
    const float* x_pkg   = (const float*)d_in[0];
    const float* x_tgt   = (const float*)d_in[1];
    const int*   src_idx = (const int*)d_in[2];
    const int*   tgt_idx = (const int*)d_in[3];
    const float* W1s     = (const float*)d_in[4];
    const float* W1t     = (const float*)d_in[5];
    const float* a1      = (const float*)d_in[6];
    const float* Wpkg    = (const float*)d_in[7];
    const float* Wassign = (const float*)d_in[8];
    const float* W2s     = (const float*)d_in[9];
    const float* W2t     = (const float*)d_in[10];
    const float* a2      = (const float*)d_in[11];
    const float* Wcls    = (const float*)d_in[12];
    const float* bcls    = (const float*)d_in[13];
    float* out = (float*)d_out;

    void* ap = nullptr;
    cudaGetSymbolAddress(&ap, g_arena);
    char* AR = (char*)ap;
    float* l_all = (float*)(AR + O_LALL);
    float* r_all = (float*)(AR + O_RALL);
    float* hpkg  = (float*)(AR + O_HPKG);
    float* htgt  = (float*)(AR + O_HTGT);
    float* Spkg  = (float*)(AR + O_SPKG);
    float* Stgt  = (float*)(AR + O_STGT);
    float* pool  = (float*)(AR + O_POOL);
    float* Mpkg  = (float*)(AR + O_MPKG);
    float* Mt    = (float*)(AR + O_MT);
    float* Apool = (float*)(AR + O_APOOL);
    float* l2    = (float*)(AR + O_L2);
    float* r2    = (float*)(AR + O_R2);
    float* esc   = (float*)(AR + O_ESC);
    float* emax  = (float*)(AR + O_EMAX);
    float* eden  = (float*)(AR + O_EDEN);
    float* scal  = (float*)(AR + O_SCAL);
    bf16* xpkg3  = (bf16*)(AR + O_XPKG3);
    bf16* xtgt3  = (bf16*)(AR + O_XTGT3);
    bf16* W1s3   = (bf16*)(AR + O_W1S3);
    bf16* W1t3   = (bf16*)(AR + O_W1T3);
    bf16* Wpkg3  = (bf16*)(AR + O_WPKG3);
    bf16* hpkg3  = (bf16*)(AR + O_HPKG3);
    bf16* htgt3  = (bf16*)(AR + O_HTGT3);
    bf16* Was3   = (bf16*)(AR + O_WAS3);

    // --- conversions (split-bf16 triplets) ---
    cvtA_kernel<<<2048, 256>>>(x_pkg, xpkg3, FIN, KP1, (long long)NPKG * FIN);
    padA_kernel<<<256, 256>>>(xpkg3, NPKG, 3 * FIN, KP1);
    cvtA_kernel<<<4096, 256>>>(x_tgt, xtgt3, FIN, KP1, (long long)NTY * NTGTN * FIN);
    padA_kernel<<<512, 256>>>(xtgt3, (long long)NTY * NTGTN, 3 * FIN, KP1);
    cvtB_kernel<<<1024, 256>>>(W1s, W1s3, FIN, FD, KP1, (long long)NTY * FIN * FD);
    padB_kernel<<<64, 256>>>(W1s3, NTY, 3 * FIN, KP1, FD);
    cvtB_kernel<<<1024, 256>>>(W1t, W1t3, FIN, FD, KP1, (long long)NTY * FIN * FD);
    padB_kernel<<<64, 256>>>(W1t3, NTY, 3 * FIN, KP1, FD);
    cvtB_kernel<<<256, 256>>>(Wpkg, Wpkg3, FIN, FD, KP1, (long long)FIN * FD);
    padB_kernel<<<16, 256>>>(Wpkg3, 1, 3 * FIN, KP1, FD);
    cvtB_kernel<<<512, 256>>>(Wassign, Was3, FD, KC, KP2, (long long)(NTY + 1) * FD * KC);

    fill_kernel<<<1, 32>>>(scal, 0.f, 16);
    fill_kernel<<<512, 256>>>(pool, 0.f, 7 * KC * FD);
    fill_kernel<<<64, 256>>>(Mpkg, 0.f, KC * KC);
    fill_kernel<<<256, 256>>>(Apool, 0.f, NTY * KC * KC);

    // --- conv1 projections on tensor cores (batched over 6 types) ---
    bmma_kernel<<<dim3(FD / 128, (NPKG + 127) / 128, NTY), 256>>>(
        xpkg3, W1s3, l_all, NPKG, FD, KP1, 0,
        0LL, (long long)KP1 * FD, (long long)NPKG * FD);
    bmma_kernel<<<dim3(FD / 128, (NTGTN + 127) / 128, NTY), 256>>>(
        xtgt3, W1t3, r_all, NTGTN, FD, KP1, 0,
        (long long)NTGTN * KP1, (long long)KP1 * FD, (long long)NTGTN * FD);

    // --- pkg side ---
    bmma_kernel<<<dim3(FD / 128, (NPKG + 127) / 128), 256>>>(
        xpkg3, Wpkg3, hpkg, NPKG, FD, KP1, 1, 0, 0, 0);
    cvtA_kernel<<<2048, 256>>>(hpkg, hpkg3, FD, KP2, (long long)NPKG * FD);
    bmma_kernel<<<dim3(1, (NPKG + 127) / 128), 256>>>(
        hpkg3, Was3, Spkg, NPKG, KC, KP2, 0, 0, 0, 0);
    softmax_ent_kernel<<<(NPKG + 7) / 8, 256>>>(Spkg, NPKG, 1.0f / NPKG, scal);
    atb_kernel<<<dim3(FD / 64, KC / 64, 64), 256>>>(Spkg, hpkg, pool, NPKG, KC, FD);
    atb_kernel<<<dim3(KC / 64, KC / 64, 64), 256>>>(Spkg, Spkg, Mpkg, NPKG, KC, KC);

    for (int t = 0; t < NTY; t++) {
        const float* bl  = l_all + (long long)t * NPKG * FD;
        const float* brr = r_all + (long long)t * NTGTN * FD;
        const int* se = src_idx + (long long)t * NE;
        const int* te = tgt_idx + (long long)t * NE;

        fill_kernel<<<128, 256>>>(emax, -INFINITY, NTGTN * 4);
        fill_kernel<<<128, 256>>>(eden, 0.f, NTGTN * 4);
        fill_kernel<<<1024, 256>>>(htgt, 0.f, NTGTN * FD);

        edge_score_kernel<<<NE * 32 / 256, 256>>>(bl, brr, se, te, a1 + t * 256, esc, emax);
        edge_exp_kernel<<<(NE * 4 + 255) / 256, 256>>>(te, esc, emax, eden);
        edge_aggr_kernel<<<NE * 32 / 256, 256>>>(bl, se, te, esc, eden, htgt);
        relu_kernel<<<1024, 256>>>(htgt, NTGTN * FD);

        cvtA_kernel<<<2048, 256>>>(htgt, htgt3, FD, KP2, (long long)NTGTN * FD);
        bmma_kernel<<<dim3(1, (NTGTN + 127) / 128), 256>>>(
            htgt3, Was3 + (long long)(t + 1) * KP2 * KC, Stgt, NTGTN, KC, KP2, 0, 0, 0, 0);
        softmax_ent_kernel<<<(NTGTN + 7) / 8, 256>>>(Stgt, NTGTN, 1.0f / NTGTN, scal);

        atb_kernel<<<dim3(FD / 64, KC / 64, 64), 256>>>(
            Stgt, htgt, pool + (long long)(t + 1) * KC * FD, NTGTN, KC, FD);
        fill_kernel<<<64, 256>>>(Mt, 0.f, KC * KC);
        atb_kernel<<<dim3(KC / 64, KC / 64, 64), 256>>>(Stgt, Stgt, Mt, NTGTN, KC, KC);

        edge_dot_kernel<<<NE * 32 / 256, 256>>>(Spkg, Stgt, se, te, scal + 2);
        mulsum_kernel<<<8, 256>>>(Mpkg, Mt, KC * KC, scal + 3);
        link_combine_kernel<<<1, 1>>>(scal);

        apool_kernel<<<896, 256>>>(Spkg, Stgt, se, te, Apool + (long long)t * KC * KC);
    }

    // conv2 projections (small; fp32)
    sgemm_kernel<<<dim3(FD / 64, KC / 64, NTY), 256>>>(
        pool, W2s, l2, KC, FD, FD, 0, (long long)FD * FD, (long long)KC * FD);
    sgemm_kernel<<<dim3(FD / 64, KC / 64, NTY), 256>>>(
        pool + (long long)KC * FD, W2t, r2, KC, FD, FD,
        (long long)KC * FD, (long long)FD * FD, (long long)KC * FD);

    attn2_score_kernel<<<NTY * KC * KC * 32 / 256, 256>>>(l2, r2, Apool, a2, esc);
    attn2_softmax_kernel<<<dim3(KC, NTY), 128>>>(esc, out + (NTY + 1) * KC + 1);

    cls_kernel<<<(NTY + 1) * KC * 32 / 256, 256>>>(pool, Wcls, bcls, out);
    finalize_kernel<<<1, 1>>>(scal, out);
}

// round 7
// speedup vs baseline: 1.4829x; 1.2760x over previous
#include <cuda_runtime.h>
#include <cuda_bf16.h>
#include <math.h>

#define NPKG  20000
#define NTGTN 30000
#define NE    100000
#define NTY   6
#define FIN   400
#define FD    256
#define KC    128
#define KP1   1216   // padded 3*400
#define KP2   768    // 3*256
#define EB    12500  // edge blocks per type (NE*32/256)

// ---------------- byte-offset arena ----------------
#define O_LALL   0LL            // 6*20000*256*4
#define O_RALL   122880000LL    // 6*30000*256*4
#define O_GST    0LL            // alias: 6*128*100000*2 (after l_all dead)
#define O_GT     153600000LL    // alias: 6*100000*128*2 (after r_all dead)
#define O_HPKG   307200000LL
#define O_HTGT   327680000LL    // 6*30000*256*4
#define O_SPKG   512000000LL
#define O_STGT   522240000LL    // 6*30000*128*4
#define O_POOL   614400000LL
#define O_MPKG   615317504LL
#define O_MT     615383040LL    // 6*128*128*4
#define O_APOOL  615776256LL    // 6*128*128*4
#define O_L2     616169472LL
#define O_R2     616955904LL
#define O_ESC    617742336LL    // 6*NE*4*4
#define O_EMAX   627342336LL
#define O_EDEN   630222336LL
#define O_SCAL   633102336LL
#define O_XPKG3  633102592LL    // 20000*1216*2
#define O_XTGT3  681742592LL    // 6*30000*1216*2
#define O_HTGTB  681742592LL    // alias (xtgt3 dead after conv1): 6*90000*256*2
#define O_W1S3   1119502592LL
#define O_W1T3   1123238144LL
#define O_WPKG3  1126973696LL
#define O_HPKG3  1127596288LL   // 20000*768*2
#define O_HTGT3  1158316288LL   // 6*30000*768*2
#define O_WAS3   1434796288LL
#define O_STPA   1436172544LL   // 128*60000*2
#define O_SPB    1451532544LL   // 60000*128*2
#define O_HPKGB  1466892544LL   // 60000*256*2
#define O_STTA   1497612544LL   // 6*128*90000*2
#define O_STGB   1635852544LL   // 6*90000*128*2
#define ARENA_BYTES 1774092544LL

__device__ __align__(256) char g_arena[ARENA_BYTES];

typedef __nv_bfloat16 bf16;

__device__ __forceinline__ void atomicMaxFloat(float* addr, float val) {
    int old = __float_as_int(*addr);
    while (__int_as_float(old) < val) {
        int prev = atomicCAS((int*)addr, old, __float_as_int(val));
        if (prev == old) break;
        old = prev;
    }
}

__global__ void fill_kernel(float* __restrict__ p, float v, long long n) {
    for (long long i = blockIdx.x * (long long)blockDim.x + threadIdx.x; i < n;
         i += (long long)gridDim.x * blockDim.x) p[i] = v;
}

__global__ void relu_kernel(float* __restrict__ p, long long n) {
    for (long long i = blockIdx.x * (long long)blockDim.x + threadIdx.x; i < n;
         i += (long long)gridDim.x * blockDim.x) p[i] = fmaxf(p[i], 0.f);
}

// ---------- fp32 -> split-bf16 triplet conversions ----------
__global__ void cvtA_kernel(const float* __restrict__ X, bf16* __restrict__ Y,
                            int K, int Kp, long long total)
{
    for (long long i = blockIdx.x * (long long)blockDim.x + threadIdx.x; i < total;
         i += (long long)gridDim.x * blockDim.x) {
        long long r = i / K;
        int k = (int)(i - r * K);
        float x = X[i];
        bf16 h = __float2bfloat16(x);
        bf16 lo = __float2bfloat16(x - __bfloat162float(h));
        bf16* row = Y + r * Kp + 3 * k;
        row[0] = h; row[1] = h; row[2] = lo;
    }
}
__global__ void padA_kernel(bf16* __restrict__ Y, long long rows, int K3, int Kp) {
    int pw = Kp - K3;
    long long total = rows * pw;
    for (long long i = blockIdx.x * (long long)blockDim.x + threadIdx.x; i < total;
         i += (long long)gridDim.x * blockDim.x) {
        long long r = i / pw;
        Y[r * Kp + K3 + (int)(i - r * pw)] = __float2bfloat16(0.f);
    }
}
__global__ void cvtB_kernel(const float* __restrict__ X, bf16* __restrict__ Y,
                            int K, int N, int Kp, long long total)
{
    long long KN = (long long)K * N;
    for (long long i = blockIdx.x * (long long)blockDim.x + threadIdx.x; i < total;
         i += (long long)gridDim.x * blockDim.x) {
        long long b = i / KN;
        long long rem = i - b * KN;
        int k = (int)(rem / N), n = (int)(rem - (long long)k * N);
        float x = X[i];
        bf16 h = __float2bfloat16(x);
        bf16 lo = __float2bfloat16(x - __bfloat162float(h));
        bf16* base = Y + (b * (long long)Kp + 3 * k) * N + n;
        base[0] = h; base[N] = lo; base[2 * N] = h;
    }
}
__global__ void padB_kernel(bf16* __restrict__ Y, int nb, int K3, int Kp, int N) {
    long long total = (long long)nb * (Kp - K3) * N;
    int pw = Kp - K3;
    for (long long i = blockIdx.x * (long long)blockDim.x + threadIdx.x; i < total;
         i += (long long)gridDim.x * blockDim.x) {
        long long b = i / ((long long)pw * N);
        long long rem = i - b * (long long)pw * N;
        int k = (int)(rem / N), n = (int)(rem % N);
        Y[(b * (long long)Kp + K3 + k) * N + n] = __float2bfloat16(0.f);
    }
}
// transpose-split: S[N][C] -> T[C][3N]  (A-form for S^T GEMMs)
__global__ void cvtT_kernel(const float* __restrict__ S, bf16* __restrict__ T,
                            int N, int C, long long sS, long long sT)
{
    S += blockIdx.z * sS; T += blockIdx.z * sT;
    __shared__ float tile[32][33];
    int n0 = blockIdx.x * 32, c0 = blockIdx.y * 32;
    int tx = threadIdx.x & 31, ty = threadIdx.x >> 5;
    for (int i = ty; i < 32; i += 8) {
        int n = n0 + i;
        tile[i][tx] = (n < N) ? S[(long long)n * C + c0 + tx] : 0.f;
    }
    __syncthreads();
    for (int i = ty; i < 32; i += 8) {
        int n = n0 + tx;
        if (n < N) {
            float x = tile[tx][i];
            bf16 h = __float2bfloat16(x);
            bf16 lo = __float2bfloat16(x - __bfloat162float(h));
            bf16* p = T + (long long)(c0 + i) * (3LL * N) + 3 * n;
            p[0] = h; p[1] = h; p[2] = lo;
        }
    }
}
// gathered transpose (plain bf16): out[t][c][e] = S[idx[t][e]][c]
__global__ void gatherT_kernel(const float* __restrict__ S, const int* __restrict__ idx_all,
                               bf16* __restrict__ out)
{
    int t = blockIdx.z;
    const int* idx = idx_all + (long long)t * NE;
    bf16* O = out + (long long)t * KC * NE;
    __shared__ float tile[32][33];
    int e0 = blockIdx.x * 32, c0 = blockIdx.y * 32;
    int tx = threadIdx.x & 31, ty = threadIdx.x >> 5;
    for (int i = ty; i < 32; i += 8)
        tile[i][tx] = S[(long long)idx[e0 + i] * KC + c0 + tx];
    __syncthreads();
    for (int i = ty; i < 32; i += 8)
        O[(long long)(c0 + i) * NE + e0 + tx] = __float2bfloat16(tile[tx][i]);
}
// gathered rows (plain bf16): out[t][e][c] = S[t][idx[t][e]][c]
__global__ void gatherB_kernel(const float* __restrict__ S_all, const int* __restrict__ idx_all,
                               bf16* __restrict__ out, long long sS)
{
    long long total = (long long)NTY * NE * KC;
    for (long long i = blockIdx.x * (long long)blockDim.x + threadIdx.x; i < total;
         i += (long long)gridDim.x * blockDim.x) {
        long long eg = i >> 7;
        int c = (int)(i & 127);
        int t = (int)(eg / NE);
        int e = (int)(eg - (long long)t * NE);
        out[i] = __float2bfloat16(
            S_all[t * sS + (long long)idx_all[(long long)t * NE + e] * KC + c]);
    }
}

// ---------- bf16 tensor-core GEMM: C[M,N] = A[M,Kp] @ B[Kp,N] ----------
__global__ __launch_bounds__(256) void bmma_kernel(
    const bf16* __restrict__ A, const bf16* __restrict__ B, float* __restrict__ C,
    int M, int N, int Kp, int do_relu, long long sA, long long sB, long long sC)
{
    A += (long long)blockIdx.z * sA;
    B += (long long)blockIdx.z * sB;
    C += (long long)blockIdx.z * sC;
    __shared__ bf16 As[128 * 40];
    __shared__ bf16 Bs[32 * 136];
    const int tid = threadIdx.x;
    const int w = tid >> 5, l = tid & 31;
    const int wm = w & 1, wn = w >> 1;
    const int bm = blockIdx.y << 7, bn = blockIdx.x << 7;

    float acc[4][4][4];
#pragma unroll
    for (int a = 0; a < 4; a++)
#pragma unroll
        for (int b = 0; b < 4; b++)
#pragma unroll
            for (int c = 0; c < 4; c++) acc[a][b][c] = 0.f;

    unsigned a_addr[4], b_addr[4];
#pragma unroll
    for (int mt = 0; mt < 4; mt++) {
        int row = wm * 64 + mt * 16 + (l & 7) + ((l >> 3) & 1) * 8;
        int col = (l >> 4) << 3;
        a_addr[mt] = (unsigned)__cvta_generic_to_shared(&As[row * 40 + col]);
    }
#pragma unroll
    for (int nt = 0; nt < 4; nt++) {
        int krow = l & 15;
        int col = wn * 32 + nt * 8;
        b_addr[nt] = (unsigned)__cvta_generic_to_shared(&Bs[krow * 136 + col]);
    }

    for (int k0 = 0; k0 < Kp; k0 += 32) {
#pragma unroll
        for (int it = 0; it < 2; it++) {
            int slot = tid + it * 256;
            int row = slot >> 2, grp = (slot & 3) << 3;
            uint4 v = make_uint4(0u, 0u, 0u, 0u);
            if (bm + row < M)
                v = *(const uint4*)(A + (long long)(bm + row) * Kp + k0 + grp);
            *(uint4*)&As[row * 40 + grp] = v;
        }
#pragma unroll
        for (int it = 0; it < 2; it++) {
            int slot = tid + it * 256;
            int kk = slot >> 4, grp = (slot & 15) << 3;
            *(uint4*)&Bs[kk * 136 + grp] =
                *(const uint4*)(B + (long long)(k0 + kk) * N + bn + grp);
        }
        __syncthreads();
#pragma unroll
        for (int s = 0; s < 2; s++) {
            unsigned af[4][4], bfr[4][2];
#pragma unroll
            for (int mt = 0; mt < 4; mt++)
                asm volatile("ldmatrix.sync.aligned.m8n8.x4.shared.b16 {%0,%1,%2,%3}, [%4];"
                    : "=r"(af[mt][0]), "=r"(af[mt][1]), "=r"(af[mt][2]), "=r"(af[mt][3])
                    : "r"(a_addr[mt] + s * 32));
#pragma unroll
            for (int nt = 0; nt < 4; nt++)
                asm volatile("ldmatrix.sync.aligned.m8n8.x2.trans.shared.b16 {%0,%1}, [%2];"
                    : "=r"(bfr[nt][0]), "=r"(bfr[nt][1])
                    : "r"(b_addr[nt] + s * 4352));
#pragma unroll
            for (int mt = 0; mt < 4; mt++)
#pragma unroll
                for (int nt = 0; nt < 4; nt++)
                    asm volatile(
                        "mma.sync.aligned.m16n8k16.row.col.f32.bf16.bf16.f32 "
                        "{%0,%1,%2,%3}, {%4,%5,%6,%7}, {%8,%9}, {%0,%1,%2,%3};"
                        : "+f"(acc[mt][nt][0]), "+f"(acc[mt][nt][1]),
                          "+f"(acc[mt][nt][2]), "+f"(acc[mt][nt][3])
                        : "r"(af[mt][0]), "r"(af[mt][1]), "r"(af[mt][2]), "r"(af[mt][3]),
                          "r"(bfr[nt][0]), "r"(bfr[nt][1]));
        }
        __syncthreads();
    }
#pragma unroll
    for (int mt = 0; mt < 4; mt++) {
        int rr = bm + wm * 64 + mt * 16 + (l >> 2);
#pragma unroll
        for (int nt = 0; nt < 4; nt++) {
            int cc = bn + wn * 32 + nt * 8 + ((l & 3) << 1);
            float c0 = acc[mt][nt][0], c1 = acc[mt][nt][1];
            float c2 = acc[mt][nt][2], c3 = acc[mt][nt][3];
            if (do_relu) {
                c0 = fmaxf(c0, 0.f); c1 = fmaxf(c1, 0.f);
                c2 = fmaxf(c2, 0.f); c3 = fmaxf(c3, 0.f);
            }
            if (rr < M) {
                C[(long long)rr * N + cc] = c0;
                C[(long long)rr * N + cc + 1] = c1;
            }
            if (rr + 8 < M) {
                C[(long long)(rr + 8) * N + cc] = c2;
                C[(long long)(rr + 8) * N + cc + 1] = c3;
            }
        }
    }
}

// ---------- split-K bf16 MMA with atomic fp32 epilogue; M=128 fixed ----------
// z = batch*nsplit + split. Guards handle Kreal not multiple of 32.
__global__ __launch_bounds__(256) void bmma_split_kernel(
    const bf16* __restrict__ A, const bf16* __restrict__ B, float* __restrict__ C,
    int N, int Kp, int Kreal, int nsplit, int kchunk,
    long long sA, long long sB, long long sC)
{
    int batch = blockIdx.z / nsplit, split = blockIdx.z - batch * nsplit;
    A += (long long)batch * sA;
    B += (long long)batch * sB;
    C += (long long)batch * sC;
    int kbeg = split * kchunk;
    int kend = min(kbeg + kchunk, Kreal);
    __shared__ bf16 As[128 * 40];
    __shared__ bf16 Bs[32 * 136];
    const int tid = threadIdx.x;
    const int w = tid >> 5, l = tid & 31;
    const int wm = w & 1, wn = w >> 1;
    const int bn = blockIdx.x << 7;

    float acc[4][4][4];
#pragma unroll
    for (int a = 0; a < 4; a++)
#pragma unroll
        for (int b = 0; b < 4; b++)
#pragma unroll
            for (int c = 0; c < 4; c++) acc[a][b][c] = 0.f;

    unsigned a_addr[4], b_addr[4];
#pragma unroll
    for (int mt = 0; mt < 4; mt++) {
        int row = wm * 64 + mt * 16 + (l & 7) + ((l >> 3) & 1) * 8;
        int col = (l >> 4) << 3;
        a_addr[mt] = (unsigned)__cvta_generic_to_shared(&As[row * 40 + col]);
    }
#pragma unroll
    for (int nt = 0; nt < 4; nt++) {
        int krow = l & 15;
        int col = wn * 32 + nt * 8;
        b_addr[nt] = (unsigned)__cvta_generic_to_shared(&Bs[krow * 136 + col]);
    }

    for (int k0 = kbeg; k0 < kend; k0 += 32) {
#pragma unroll
        for (int it = 0; it < 2; it++) {
            int slot = tid + it * 256;
            int row = slot >> 2, grp = (slot & 3) << 3;
            uint4 v = make_uint4(0u, 0u, 0u, 0u);
            if (k0 + grp + 8 <= Kreal)
                v = *(const uint4*)(A + (long long)row * Kp + k0 + grp);
            *(uint4*)&As[row * 40 + grp] = v;
        }
#pragma unroll
        for (int it = 0; it < 2; it++) {
            int slot = tid + it * 256;
            int kk = slot >> 4, grp = (slot & 15) << 3;
            uint4 v = make_uint4(0u, 0u, 0u, 0u);
            if (k0 + kk < Kreal)
                v = *(const uint4*)(B + (long long)(k0 + kk) * N + bn + grp);
            *(uint4*)&Bs[kk * 136 + grp] = v;
        }
        __syncthreads();
#pragma unroll
        for (int s = 0; s < 2; s++) {
            unsigned af[4][4], bfr[4][2];
#pragma unroll
            for (int mt = 0; mt < 4; mt++)
                asm volatile("ldmatrix.sync.aligned.m8n8.x4.shared.b16 {%0,%1,%2,%3}, [%4];"
                    : "=r"(af[mt][0]), "=r"(af[mt][1]), "=r"(af[mt][2]), "=r"(af[mt][3])
                    : "r"(a_addr[mt] + s * 32));
#pragma unroll
            for (int nt = 0; nt < 4; nt++)
                asm volatile("ldmatrix.sync.aligned.m8n8.x2.trans.shared.b16 {%0,%1}, [%2];"
                    : "=r"(bfr[nt][0]), "=r"(bfr[nt][1])
                    : "r"(b_addr[nt] + s * 4352));
#pragma unroll
            for (int mt = 0; mt < 4; mt++)
#pragma unroll
                for (int nt = 0; nt < 4; nt++)
                    asm volatile(
                        "mma.sync.aligned.m16n8k16.row.col.f32.bf16.bf16.f32 "
                        "{%0,%1,%2,%3}, {%4,%5,%6,%7}, {%8,%9}, {%0,%1,%2,%3};"
                        : "+f"(acc[mt][nt][0]), "+f"(acc[mt][nt][1]),
                          "+f"(acc[mt][nt][2]), "+f"(acc[mt][nt][3])
                        : "r"(af[mt][0]), "r"(af[mt][1]), "r"(af[mt][2]), "r"(af[mt][3]),
                          "r"(bfr[nt][0]), "r"(bfr[nt][1]));
        }
        __syncthreads();
    }
#pragma unroll
    for (int mt = 0; mt < 4; mt++) {
        int rr = wm * 64 + mt * 16 + (l >> 2);
#pragma unroll
        for (int nt = 0; nt < 4; nt++) {
            int cc = bn + wn * 32 + nt * 8 + ((l & 3) << 1);
            atomicAdd(&C[(long long)rr * N + cc],     acc[mt][nt][0]);
            atomicAdd(&C[(long long)rr * N + cc + 1], acc[mt][nt][1]);
            atomicAdd(&C[(long long)(rr + 8) * N + cc],     acc[mt][nt][2]);
            atomicAdd(&C[(long long)(rr + 8) * N + cc + 1], acc[mt][nt][3]);
        }
    }
}

// ---------- fp32 SGEMM (small conv2 GEMMs only) ----------
__global__ __launch_bounds__(256) void sgemm_kernel(
    const float* __restrict__ A, const float* __restrict__ B, float* __restrict__ C,
    int M, int N, int Kd, long long sA, long long sB, long long sC)
{
    A += (long long)blockIdx.z * sA; B += (long long)blockIdx.z * sB;
    C += (long long)blockIdx.z * sC;
    __shared__ float As[16][68], Bs[16][68];
    const int tid = threadIdx.x, tx = tid & 15, ty = tid >> 4;
    const int bm = blockIdx.y << 6, bn = blockIdx.x << 6;
    const int arow = tid >> 2, acol = (tid & 3) << 2;
    const int brow = tid >> 4, bcol = (tid & 15) << 2;
    float acc[4][4];
#pragma unroll
    for (int i = 0; i < 4; i++)
#pragma unroll
        for (int j = 0; j < 4; j++) acc[i][j] = 0.f;
    const int gr = bm + arow;
    for (int k0 = 0; k0 < Kd; k0 += 16) {
        float4 av = make_float4(0.f, 0.f, 0.f, 0.f);
        if (gr < M) av = *(const float4*)(A + (long long)gr * Kd + k0 + acol);
        As[acol][arow] = av.x; As[acol + 1][arow] = av.y;
        As[acol + 2][arow] = av.z; As[acol + 3][arow] = av.w;
        *(float4*)&Bs[brow][bcol] = *(const float4*)(B + (long long)(k0 + brow) * N + bn + bcol);
        __syncthreads();
#pragma unroll
        for (int k = 0; k < 16; k++) {
            float4 a4 = *(const float4*)&As[k][ty << 2];
            float4 b4 = *(const float4*)&Bs[k][tx << 2];
            float ar[4] = {a4.x, a4.y, a4.z, a4.w};
            float br_[4] = {b4.x, b4.y, b4.z, b4.w};
#pragma unroll
            for (int i = 0; i < 4; i++)
#pragma unroll
                for (int j = 0; j < 4; j++) acc[i][j] = fmaf(ar[i], br_[j], acc[i][j]);
        }
        __syncthreads();
    }
#pragma unroll
    for (int i = 0; i < 4; i++) {
        int r = bm + (ty << 2) + i;
        if (r >= M) continue;
        *(float4*)(C + (long long)r * N + bn + (tx << 2)) =
            make_float4(acc[i][0], acc[i][1], acc[i][2], acc[i][3]);
    }
}

// rows of width 128: softmax in-place + entropy (warp per row)
__global__ void softmax_ent_kernel(float* __restrict__ S, int N, float inv_n,
                                   float* __restrict__ ent_acc)
{
    int g = blockIdx.x * blockDim.x + threadIdx.x;
    int w = g >> 5, lane = g & 31;
    if (w >= N) return;
    float* row = S + (long long)w * KC;
    float v0 = row[lane], v1 = row[lane + 32], v2 = row[lane + 64], v3 = row[lane + 96];
    float m = fmaxf(fmaxf(v0, v1), fmaxf(v2, v3));
    for (int o = 16; o; o >>= 1) m = fmaxf(m, __shfl_xor_sync(~0u, m, o));
    v0 = expf(v0 - m); v1 = expf(v1 - m); v2 = expf(v2 - m); v3 = expf(v3 - m);
    float s = v0 + v1 + v2 + v3;
    for (int o = 16; o; o >>= 1) s += __shfl_xor_sync(~0u, s, o);
    float inv = 1.f / s;
    v0 *= inv; v1 *= inv; v2 *= inv; v3 *= inv;
    row[lane] = v0; row[lane + 32] = v1; row[lane + 64] = v2; row[lane + 96] = v3;
    float e = -(v0 * logf(v0 + 1e-15f) + v1 * logf(v1 + 1e-15f)
              + v2 * logf(v2 + 1e-15f) + v3 * logf(v3 + 1e-15f));
    for (int o = 16; o; o >>= 1) e += __shfl_xor_sync(~0u, e, o);
    if (lane == 0) atomicAdd(ent_acc, e * inv_n);
}

// ---------- batched edge kernels (type = blockIdx.x / EB) ----------
__global__ __launch_bounds__(256) void edge_score_kernel(
    const float* __restrict__ l_all, const float* __restrict__ r_all,
    const int* __restrict__ src_all, const int* __restrict__ tgt_all,
    const float* __restrict__ a1_all, float* __restrict__ esc_all,
    float* __restrict__ emax_all)
{
    int t = blockIdx.x / EB;
    const float* l = l_all + (long long)t * NPKG * FD;
    const float* r = r_all + (long long)t * NTGTN * FD;
    const int* src = src_all + (long long)t * NE;
    const int* tgt = tgt_all + (long long)t * NE;
    float* esc = esc_all + (long long)t * NE * 4;
    float* emax = emax_all + (long long)t * NTGTN * 4;
    __shared__ float a_s[256];
    int tid = threadIdx.x;
    a_s[tid] = a1_all[t * 256 + tid];
    __syncthreads();
    int e = (((blockIdx.x - t * EB) * 256) + tid) >> 5;
    int lane = tid & 31;
    int tg = tgt[e];
    const float* lr = l + (long long)src[e] * FD;
    const float* rr = r + (long long)tg * FD;
#pragma unroll
    for (int h = 0; h < 4; h++) {
        float acc = 0.f;
#pragma unroll
        for (int q = 0; q < 2; q++) {
            int c = h * 64 + lane + q * 32;
            float v = lr[c] + rr[c];
            v = v > 0.f ? v : 0.2f * v;
            acc = fmaf(v, a_s[c], acc);
        }
        for (int o = 16; o; o >>= 1) acc += __shfl_xor_sync(~0u, acc, o);
        if (lane == 0) { esc[e * 4 + h] = acc; atomicMaxFloat(&emax[tg * 4 + h], acc); }
    }
}

__global__ void edge_exp_kernel(const int* __restrict__ tgt_all, float* __restrict__ esc_all,
                                const float* __restrict__ emax_all, float* __restrict__ eden_all)
{
    long long idx = blockIdx.x * (long long)blockDim.x + threadIdx.x;
    if (idx >= (long long)NTY * NE * 4) return;
    int t = (int)(idx / ((long long)NE * 4));
    long long rem = idx - (long long)t * NE * 4;
    int e = (int)(rem >> 2), h = (int)(rem & 3);
    int tg = tgt_all[(long long)t * NE + e];
    float m = emax_all[(long long)t * NTGTN * 4 + tg * 4 + h];
    if (!isfinite(m)) m = 0.f;
    float ex = expf(esc_all[idx] - m);
    esc_all[idx] = ex;
    atomicAdd(&eden_all[(long long)t * NTGTN * 4 + tg * 4 + h], ex);
}

__global__ __launch_bounds__(256) void edge_aggr_kernel(
    const float* __restrict__ l_all, const int* __restrict__ src_all,
    const int* __restrict__ tgt_all, const float* __restrict__ esc_all,
    const float* __restrict__ eden_all, float* __restrict__ htgt_all)
{
    int t = blockIdx.x / EB;
    const float* l = l_all + (long long)t * NPKG * FD;
    const int* src = src_all + (long long)t * NE;
    const int* tgt = tgt_all + (long long)t * NE;
    const float* esc = esc_all + (long long)t * NE * 4;
    const float* eden = eden_all + (long long)t * NTGTN * 4;
    float* outh = htgt_all + (long long)t * NTGTN * FD;
    int tid = threadIdx.x;
    int e = (((blockIdx.x - t * EB) * 256) + tid) >> 5;
    int lane = tid & 31;
    int s = src[e], tg = tgt[e];
    float alpha[4];
#pragma unroll
    for (int h = 0; h < 4; h++)
        alpha[h] = esc[e * 4 + h] / (eden[tg * 4 + h] + 1e-16f);
    const float* lr = l + (long long)s * FD;
    float* orow = outh + (long long)tg * FD;
#pragma unroll
    for (int q = 0; q < 8; q++) {
        int c = lane + q * 32;
        atomicAdd(&orow[c], lr[c] * alpha[c >> 6]);
    }
}

// batched mulsum: slot[blockIdx.y] += sum(a .* b_y)
__global__ void mulsum_kernel(const float* __restrict__ a, const float* __restrict__ b_all,
                              int n, float* __restrict__ slots)
{
    const float* b = b_all + (long long)blockIdx.y * n;
    __shared__ float sred[8];
    float acc = 0.f;
    for (int i = blockIdx.x * blockDim.x + threadIdx.x; i < n; i += gridDim.x * blockDim.x)
        acc += a[i] * b[i];
    for (int o = 16; o; o >>= 1) acc += __shfl_xor_sync(~0u, acc, o);
    if ((threadIdx.x & 31) == 0) sred[threadIdx.x >> 5] = acc;
    __syncthreads();
    if (threadIdx.x == 0) {
        float t = 0.f;
        for (int i = 0; i < 8; i++) t += sred[i];
        atomicAdd(&slots[blockIdx.y], t);
    }
}

// link loss: dot_t = trace(Apool_t); termM_t = scal[16+t]
__global__ void link_kernel(const float* __restrict__ Apool_all, float* __restrict__ scal) {
    __shared__ float red[4];
    int tid = threadIdx.x;  // 128
    float link = 0.f;
    for (int t = 0; t < NTY; t++) {
        float d = Apool_all[t * KC * KC + tid * (KC + 1)];
        for (int o = 16; o; o >>= 1) d += __shfl_xor_sync(~0u, d, o);
        if ((tid & 31) == 0) red[tid >> 5] = d;
        __syncthreads();
        if (tid == 0) {
            float dot = red[0] + red[1] + red[2] + red[3];
            float n2 = fmaxf((float)NE - 2.f * dot + scal[16 + t], 0.f) + 1e-12f;
            link += sqrtf(n2) * (1.f / ((float)NPKG * (float)NTGTN));
        }
        __syncthreads();
    }
    if (tid == 0) scal[1] = link;
}

__global__ __launch_bounds__(256) void attn2_score_kernel(
    const float* __restrict__ l2, const float* __restrict__ r2,
    const float* __restrict__ Apool, const float* __restrict__ a2, float* __restrict__ e2)
{
    int g = blockIdx.x * blockDim.x + threadIdx.x;
    int w = g >> 5, lane = g & 31;
    if (w >= NTY * KC * KC) return;
    int t = w >> 14, rem = w & 16383, i = rem >> 7, j = rem & 127;
    const float* li = l2 + ((long long)t * KC + i) * FD;
    const float* rj = r2 + ((long long)t * KC + j) * FD;
    const float* av = a2 + t * 256;
    float ap = Apool[(long long)t * KC * KC + i * KC + j];
#pragma unroll
    for (int h = 0; h < 4; h++) {
        float acc = 0.f;
#pragma unroll
        for (int q = 0; q < 2; q++) {
            int c = h * 64 + lane + q * 32;
            float v = li[c] + rj[c];
            v = v > 0.f ? v : 0.2f * v;
            acc = fmaf(v, av[c], acc);
        }
        for (int o = 16; o; o >>= 1) acc += __shfl_xor_sync(~0u, acc, o);
        if (lane == 0) e2[(long long)w * 4 + h] = (ap > 0.f) ? acc : -1e9f;
    }
}

__global__ __launch_bounds__(128) void attn2_softmax_kernel(
    const float* __restrict__ e2, float* __restrict__ out_attn)
{
    int j = blockIdx.x, t = blockIdx.y, i = threadIdx.x;
    int lane = i & 31, wid = i >> 5;
    __shared__ float wred[4][4];
    long long base = (((long long)t * KC + i) * KC + j) * 4;
    float e[4], m[4], ex[4];
#pragma unroll
    for (int h = 0; h < 4; h++) e[h] = e2[base + h];
#pragma unroll
    for (int h = 0; h < 4; h++) {
        float x = e[h];
        for (int o = 16; o; o >>= 1) x = fmaxf(x, __shfl_xor_sync(~0u, x, o));
        if (lane == 0) wred[wid][h] = x;
    }
    __syncthreads();
#pragma unroll
    for (int h = 0; h < 4; h++)
        m[h] = fmaxf(fmaxf(wred[0][h], wred[1][h]), fmaxf(wred[2][h], wred[3][h]));
    __syncthreads();
#pragma unroll
    for (int h = 0; h < 4; h++) {
        ex[h] = expf(e[h] - m[h]);
        float x = ex[h];
        for (int o = 16; o; o >>= 1) x += __shfl_xor_sync(~0u, x, o);
        if (lane == 0) wred[wid][h] = x;
    }
    __syncthreads();
#pragma unroll
    for (int h = 0; h < 4; h++) {
        float sm = wred[0][h] + wred[1][h] + wred[2][h] + wred[3][h];
        out_attn[base + h] = ex[h] / sm;
    }
}

__global__ void cls_kernel(const float* __restrict__ pool, const float* __restrict__ Wcls,
                           const float* __restrict__ bcls, float* __restrict__ out)
{
    int g = blockIdx.x * blockDim.x + threadIdx.x;
    int w = g >> 5, lane = g & 31;
    if (w >= (NTY + 1) * KC) return;
    const float* row = pool + (long long)w * FD;
    float acc = 0.f;
#pragma unroll
    for (int q = 0; q < 8; q++) acc += row[lane + q * 32] * Wcls[lane + q * 32];
    for (int o = 16; o; o >>= 1) acc += __shfl_xor_sync(~0u, acc, o);
    if (lane == 0) out[w] = 1.f / (1.f + expf(-(acc + bcls[0])));
}

__global__ void finalize_kernel(const float* __restrict__ scal, float* __restrict__ out) {
    out[(NTY + 1) * KC] = scal[0] + scal[1];
}

extern "C" void kernel_launch(void* const* d_in, const int* in_sizes, int n_in,
                              void* d_out, int out_size)
{
    (void)in_sizes; (void)n_in; (void)out_size;
    const float* x_pkg   = (const float*)d_in[0];
    const float* x_tgt   = (const float*)d_in[1];
    const int*   src_idx = (const int*)d_in[2];
    const int*   tgt_idx = (const int*)d_in[3];
    const float* W1s     = (const float*)d_in[4];
    const float* W1t     = (const float*)d_in[5];
    const float* a1      = (const float*)d_in[6];
    const float* Wpkg    = (const float*)d_in[7];
    const float* Wassign = (const float*)d_in[8];
    const float* W2s     = (const float*)d_in[9];
    const float* W2t     = (const float*)d_in[10];
    const float* a2      = (const float*)d_in[11];
    const float* Wcls    = (const float*)d_in[12];
    const float* bcls    = (const float*)d_in[13];
    float* out = (float*)d_out;

    void* ap = nullptr;
    cudaGetSymbolAddress(&ap, g_arena);
    char* AR = (char*)ap;
    float* l_all  = (float*)(AR + O_LALL);
    float* r_all  = (float*)(AR + O_RALL);
    bf16*  GsT    = (bf16*)(AR + O_GST);
    bf16*  Gt     = (bf16*)(AR + O_GT);
    float* hpkg   = (float*)(AR + O_HPKG);
    float* htgt   = (float*)(AR + O_HTGT);
    float* Spkg   = (float*)(AR + O_SPKG);
    float* Stgt   = (float*)(AR + O_STGT);
    float* pool   = (float*)(AR + O_POOL);
    float* Mpkg   = (float*)(AR + O_MPKG);
    float* Mt     = (float*)(AR + O_MT);
    float* Apool  = (float*)(AR + O_APOOL);
    float* l2     = (float*)(AR + O_L2);
    float* r2     = (float*)(AR + O_R2);
    float* esc    = (float*)(AR + O_ESC);
    float* emax   = (float*)(AR + O_EMAX);
    float* eden   = (float*)(AR + O_EDEN);
    float* scal   = (float*)(AR + O_SCAL);
    bf16* xpkg3   = (bf16*)(AR + O_XPKG3);
    bf16* xtgt3   = (bf16*)(AR + O_XTGT3);
    bf16* htgtB   = (bf16*)(AR + O_HTGTB);
    bf16* W1s3    = (bf16*)(AR + O_W1S3);
    bf16* W1t3    = (bf16*)(AR + O_W1T3);
    bf16* Wpkg3   = (bf16*)(AR + O_WPKG3);
    bf16* hpkg3   = (bf16*)(AR + O_HPKG3);
    bf16* htgt3   = (bf16*)(AR + O_HTGT3);
    bf16* Was3    = (bf16*)(AR + O_WAS3);
    bf16* STpA    = (bf16*)(AR + O_STPA);
    bf16* SpB     = (bf16*)(AR + O_SPB);
    bf16* hpkgB   = (bf16*)(AR + O_HPKGB);
    bf16* STtA    = (bf16*)(AR + O_STTA);
    bf16* StgB    = (bf16*)(AR + O_STGB);

    // zero accumulators
    fill_kernel<<<1, 64>>>(scal, 0.f, 32);
    fill_kernel<<<512, 256>>>(pool, 0.f, 7LL * KC * FD);
    fill_kernel<<<256, 256>>>(Mpkg, 0.f, (long long)(16384 + 6 * 16384 + 6 * 16384));
    fill_kernel<<<512, 256>>>(emax, -INFINITY, (long long)NTY * NTGTN * 4);
    fill_kernel<<<512, 256>>>(eden, 0.f, (long long)NTY * NTGTN * 4);
    fill_kernel<<<4096, 256>>>(htgt, 0.f, (long long)NTY * NTGTN * FD);

    // input conversions
    cvtA_kernel<<<2048, 256>>>(x_pkg, xpkg3, FIN, KP1, (long long)NPKG * FIN);
    padA_kernel<<<256, 256>>>(xpkg3, NPKG, 3 * FIN, KP1);
    cvtA_kernel<<<4096, 256>>>(x_tgt, xtgt3, FIN, KP1, (long long)NTY * NTGTN * FIN);
    padA_kernel<<<512, 256>>>(xtgt3, (long long)NTY * NTGTN, 3 * FIN, KP1);
    cvtB_kernel<<<1024, 256>>>(W1s, W1s3, FIN, FD, KP1, (long long)NTY * FIN * FD);
    padB_kernel<<<64, 256>>>(W1s3, NTY, 3 * FIN, KP1, FD);
    cvtB_kernel<<<1024, 256>>>(W1t, W1t3, FIN, FD, KP1, (long long)NTY * FIN * FD);
    padB_kernel<<<64, 256>>>(W1t3, NTY, 3 * FIN, KP1, FD);
    cvtB_kernel<<<256, 256>>>(Wpkg, Wpkg3, FIN, FD, KP1, (long long)FIN * FD);
    padB_kernel<<<16, 256>>>(Wpkg3, 1, 3 * FIN, KP1, FD);
    cvtB_kernel<<<512, 256>>>(Wassign, Was3, FD, KC, KP2, (long long)(NTY + 1) * FD * KC);

    // conv1 projections (tensor cores, batched over types)
    bmma_kernel<<<dim3(FD / 128, (NPKG + 127) / 128, NTY), 256>>>(
        xpkg3, W1s3, l_all, NPKG, FD, KP1, 0,
        0LL, (long long)KP1 * FD, (long long)NPKG * FD);
    bmma_kernel<<<dim3(FD / 128, (NTGTN + 127) / 128, NTY), 256>>>(
        xtgt3, W1t3, r_all, NTGTN, FD, KP1, 0,
        (long long)NTGTN * KP1, (long long)KP1 * FD, (long long)NTGTN * FD);
    bmma_kernel<<<dim3(FD / 128, (NPKG + 127) / 128), 256>>>(
        xpkg3, Wpkg3, hpkg, NPKG, FD, KP1, 1, 0, 0, 0);

    // pkg assignment + softmax
    cvtA_kernel<<<2048, 256>>>(hpkg, hpkg3, FD, KP2, (long long)NPKG * FD);
    bmma_kernel<<<dim3(1, (NPKG + 127) / 128), 256>>>(
        hpkg3, Was3, Spkg, NPKG, KC, KP2, 0, 0, 0, 0);
    softmax_ent_kernel<<<(NPKG + 7) / 8, 256>>>(Spkg, NPKG, 1.0f / NPKG, scal);

    // pkg pooled + Mpkg on tensor cores
    cvtT_kernel<<<dim3(625, 4, 1), 256>>>(Spkg, STpA, NPKG, KC, 0, 0);
    cvtB_kernel<<<512, 256>>>(Spkg, SpB, NPKG, KC, 3 * NPKG, (long long)NPKG * KC);
    cvtB_kernel<<<1024, 256>>>(hpkg, hpkgB, NPKG, FD, 3 * NPKG, (long long)NPKG * FD);
    bmma_split_kernel<<<dim3(2, 1, 15), 256>>>(
        STpA, hpkgB, pool, FD, 3 * NPKG, 3 * NPKG, 15, 4096, 0, 0, 0);
    bmma_split_kernel<<<dim3(1, 1, 15), 256>>>(
        STpA, SpB, Mpkg, KC, 3 * NPKG, 3 * NPKG, 15, 4096, 0, 0, 0);

    // edge phase (all 6 types batched)
    edge_score_kernel<<<NTY * EB, 256>>>(l_all, r_all, src_idx, tgt_idx, a1, esc, emax);
    edge_exp_kernel<<<(NTY * NE * 4 + 255) / 256, 256>>>(tgt_idx, esc, emax, eden);
    edge_aggr_kernel<<<NTY * EB, 256>>>(l_all, src_idx, tgt_idx, esc, eden, htgt);
    relu_kernel<<<4096, 256>>>(htgt, (long long)NTY * NTGTN * FD);

    // tgt assignment + softmax (batched)
    cvtA_kernel<<<4096, 256>>>(htgt, htgt3, FD, KP2, (long long)NTY * NTGTN * FD);
    bmma_kernel<<<dim3(1, (NTGTN + 127) / 128, NTY), 256>>>(
        htgt3, Was3 + (long long)KP2 * KC, Stgt, NTGTN, KC, KP2,
        0, (long long)NTGTN * KP2, (long long)KP2 * KC, (long long)NTGTN * KC);
    softmax_ent_kernel<<<(NTY * NTGTN + 7) / 8, 256>>>(Stgt, NTY * NTGTN, 1.0f / NTGTN, scal);

    // tgt pooled + Mt on tensor cores (batched over types)
    cvtT_kernel<<<dim3(938, 4, NTY), 256>>>(Stgt, STtA, NTGTN, KC,
        (long long)NTGTN * KC, (long long)KC * 3 * NTGTN);
    cvtB_kernel<<<1024, 256>>>(Stgt, StgB, NTGTN, KC, 3 * NTGTN,
        (long long)NTY * NTGTN * KC);
    cvtB_kernel<<<2048, 256>>>(htgt, htgtB, NTGTN, FD, 3 * NTGTN,
        (long long)NTY * NTGTN * FD);
    bmma_split_kernel<<<dim3(2, 1, NTY * 22), 256>>>(
        STtA, htgtB, pool + (long long)KC * FD, FD, 3 * NTGTN, 3 * NTGTN, 22, 4096,
        (long long)KC * 3 * NTGTN, (long long)3 * NTGTN * FD, (long long)KC * FD);
    bmma_split_kernel<<<dim3(1, 1, NTY * 22), 256>>>(
        STtA, StgB, Mt, KC, 3 * NTGTN, 3 * NTGTN, 22, 4096,
        (long long)KC * 3 * NTGTN, (long long)3 * NTGTN * KC, (long long)KC * KC);

    // A_pool = Gs^T @ Gt (plain bf16 gathers; sign-accuracy only needed)
    gatherT_kernel<<<dim3(NE / 32, KC / 32, NTY), 256>>>(Spkg, src_idx, GsT);
    gatherB_kernel<<<4096, 256>>>(Stgt, tgt_idx, Gt, (long long)NTGTN * KC);
    bmma_split_kernel<<<dim3(1, 1, NTY * 8), 256>>>(
        GsT, Gt, Apool, KC, NE, NE, 8, 12544,
        (long long)KC * NE, (long long)NE * KC, (long long)KC * KC);

    // link loss pieces
    mulsum_kernel<<<dim3(8, NTY), 256>>>(Mpkg, Mt, KC * KC, scal + 16);
    link_kernel<<<1, 128>>>(Apool, scal);

    // conv2 projections + attention + classifier
    sgemm_kernel<<<dim3(FD / 64, KC / 64, NTY), 256>>>(
        pool, W2s, l2, KC, FD, FD, 0, (long long)FD * FD, (long long)KC * FD);
    sgemm_kernel<<<dim3(FD / 64, KC / 64, NTY), 256>>>(
        pool + (long long)KC * FD, W2t, r2, KC, FD, FD,
        (long long)KC * FD, (long long)FD * FD, (long long)KC * FD);

    attn2_score_kernel<<<NTY * KC * KC * 32 / 256, 256>>>(l2, r2, Apool, a2, esc);
    attn2_softmax_kernel<<<dim3(KC, NTY), 128>>>(esc, out + (NTY + 1) * KC + 1);

    cls_kernel<<<(NTY + 1) * KC * 32 / 256, 256>>>(pool, Wcls, bcls, out);
    finalize_kernel<<<1, 1>>>(scal, out);
}

// round 8
// speedup vs baseline: 1.9432x; 1.3104x over previous
#include <cuda_runtime.h>
#include <cuda_bf16.h>
#include <math.h>

#define NPKG  20000
#define NTGTN 30000
#define NE    100000
#define NTY   6
#define FIN   400
#define FD    256
#define KC    128
#define KP1   1216
#define KP2   768
#define EB    12500

#define O_LALL   0LL
#define O_RALL   122880000LL
#define O_GST    0LL
#define O_GT     153600000LL
#define O_HPKG   307200000LL
#define O_HTGT   327680000LL
#define O_SPKG   512000000LL
#define O_STGT   522240000LL
#define O_POOL   614400000LL
#define O_MPKG   615317504LL
#define O_MT     615383040LL
#define O_APOOL  615776256LL
#define O_L2     616169472LL
#define O_R2     616955904LL
#define O_ESC    617742336LL
#define O_EMAX   627342336LL
#define O_EDEN   630222336LL
#define O_SCAL   633102336LL
#define O_XPKG3  633102592LL
#define O_XTGT3  681742592LL
#define O_HTGTB  681742592LL
#define O_W1S3   1119502592LL
#define O_W1T3   1123238144LL
#define O_WPKG3  1126973696LL
#define O_HPKG3  1127596288LL
#define O_HTGT3  1158316288LL
#define O_WAS3   1434796288LL
#define O_STPA   1436172544LL
#define O_SPB    1451532544LL
#define O_HPKGB  1466892544LL
#define O_STTA   1497612544LL
#define O_STGB   1635852544LL
#define ARENA_BYTES 1774092544LL

__device__ __align__(256) char g_arena[ARENA_BYTES];

typedef __nv_bfloat16 bf16;

__device__ __forceinline__ void cp16(unsigned dst, const void* src, bool pred) {
    int sz = pred ? 16 : 0;
    asm volatile("cp.async.cg.shared.global [%0], [%1], 16, %2;\n"
                 :: "r"(dst), "l"(src), "r"(sz));
}
#define CP_COMMIT() asm volatile("cp.async.commit_group;\n" ::: "memory")
#define CP_WAIT1()  asm volatile("cp.async.wait_group 1;\n" ::: "memory")
#define CP_WAIT0()  asm volatile("cp.async.wait_group 0;\n" ::: "memory")

__device__ __forceinline__ void atomicMaxFloat(float* addr, float val) {
    int old = __float_as_int(*addr);
    while (__int_as_float(old) < val) {
        int prev = atomicCAS((int*)addr, old, __float_as_int(val));
        if (prev == old) break;
        old = prev;
    }
}

__global__ void fill_kernel(float* __restrict__ p, float v, long long n) {
    for (long long i = blockIdx.x * (long long)blockDim.x + threadIdx.x; i < n;
         i += (long long)gridDim.x * blockDim.x) p[i] = v;
}

// ---------- conversions ----------
__global__ void cvtA_kernel(const float* __restrict__ X, bf16* __restrict__ Y,
                            int K, int Kp, long long total)
{
    for (long long i = blockIdx.x * (long long)blockDim.x + threadIdx.x; i < total;
         i += (long long)gridDim.x * blockDim.x) {
        long long r = i / K;
        int k = (int)(i - r * K);
        float x = X[i];
        bf16 h = __float2bfloat16(x);
        bf16 lo = __float2bfloat16(x - __bfloat162float(h));
        bf16* row = Y + r * Kp + 3 * k;
        row[0] = h; row[1] = h; row[2] = lo;
    }
}
__global__ void padA_kernel(bf16* __restrict__ Y, long long rows, int K3, int Kp) {
    int pw = Kp - K3;
    long long total = rows * pw;
    for (long long i = blockIdx.x * (long long)blockDim.x + threadIdx.x; i < total;
         i += (long long)gridDim.x * blockDim.x) {
        long long r = i / pw;
        Y[r * Kp + K3 + (int)(i - r * pw)] = __float2bfloat16(0.f);
    }
}
__global__ void cvtB_kernel(const float* __restrict__ X, bf16* __restrict__ Y,
                            int K, int N, int Kp, long long total)
{
    long long KN = (long long)K * N;
    for (long long i = blockIdx.x * (long long)blockDim.x + threadIdx.x; i < total;
         i += (long long)gridDim.x * blockDim.x) {
        long long b = i / KN;
        long long rem = i - b * KN;
        int k = (int)(rem / N), n = (int)(rem - (long long)k * N);
        float x = X[i];
        bf16 h = __float2bfloat16(x);
        bf16 lo = __float2bfloat16(x - __bfloat162float(h));
        bf16* base = Y + (b * (long long)Kp + 3 * k) * N + n;
        base[0] = h; base[N] = lo; base[2 * N] = h;
    }
}
__global__ void padB_kernel(bf16* __restrict__ Y, int nb, int K3, int Kp, int N) {
    long long total = (long long)nb * (Kp - K3) * N;
    int pw = Kp - K3;
    for (long long i = blockIdx.x * (long long)blockDim.x + threadIdx.x; i < total;
         i += (long long)gridDim.x * blockDim.x) {
        long long b = i / ((long long)pw * N);
        long long rem = i - b * (long long)pw * N;
        int k = (int)(rem / N), n = (int)(rem % N);
        Y[(b * (long long)Kp + K3 + k) * N + n] = __float2bfloat16(0.f);
    }
}
// fused: relu + A-triplet [r][3K] + B-triplet [3r][K] ; X width FD
__global__ void relu_cvt_kernel(const float* __restrict__ X, bf16* __restrict__ YA,
                                bf16* __restrict__ YB, long long total)
{
    for (long long i = blockIdx.x * (long long)blockDim.x + threadIdx.x; i < total;
         i += (long long)gridDim.x * blockDim.x) {
        long long r = i >> 8;
        int c = (int)(i & 255);
        float x = fmaxf(X[i], 0.f);
        bf16 h = __float2bfloat16(x);
        bf16 lo = __float2bfloat16(x - __bfloat162float(h));
        bf16* ra = YA + r * KP2 + 3 * c;
        ra[0] = h; ra[1] = h; ra[2] = lo;
        bf16* rb = YB + 3 * r * FD + c;
        rb[0] = h; rb[FD] = lo; rb[2 * FD] = h;
    }
}
// transpose-split: S[N][C] -> T[C][3N]
__global__ void cvtT_kernel(const float* __restrict__ S, bf16* __restrict__ T,
                            int N, int C, long long sS, long long sT)
{
    S += blockIdx.z * sS; T += blockIdx.z * sT;
    __shared__ float tile[32][33];
    int n0 = blockIdx.x * 32, c0 = blockIdx.y * 32;
    int tx = threadIdx.x & 31, ty = threadIdx.x >> 5;
    for (int i = ty; i < 32; i += 8) {
        int n = n0 + i;
        tile[i][tx] = (n < N) ? S[(long long)n * C + c0 + tx] : 0.f;
    }
    __syncthreads();
    for (int i = ty; i < 32; i += 8) {
        int n = n0 + tx;
        if (n < N) {
            float x = tile[tx][i];
            bf16 h = __float2bfloat16(x);
            bf16 lo = __float2bfloat16(x - __bfloat162float(h));
            bf16* p = T + (long long)(c0 + i) * (3LL * N) + 3 * n;
            p[0] = h; p[1] = h; p[2] = lo;
        }
    }
}
__global__ void gatherT_kernel(const float* __restrict__ S, const int* __restrict__ idx_all,
                               bf16* __restrict__ out)
{
    int t = blockIdx.z;
    const int* idx = idx_all + (long long)t * NE;
    bf16* O = out + (long long)t * KC * NE;
    __shared__ float tile[32][33];
    int e0 = blockIdx.x * 32, c0 = blockIdx.y * 32;
    int tx = threadIdx.x & 31, ty = threadIdx.x >> 5;
    for (int i = ty; i < 32; i += 8)
        tile[i][tx] = S[(long long)idx[e0 + i] * KC + c0 + tx];
    __syncthreads();
    for (int i = ty; i < 32; i += 8)
        O[(long long)(c0 + i) * NE + e0 + tx] = __float2bfloat16(tile[tx][i]);
}
__global__ void gatherB_kernel(const float* __restrict__ S_all, const int* __restrict__ idx_all,
                               bf16* __restrict__ out, long long sS)
{
    long long total = (long long)NTY * NE * KC;
    for (long long i = blockIdx.x * (long long)blockDim.x + threadIdx.x; i < total;
         i += (long long)gridDim.x * blockDim.x) {
        long long eg = i >> 7;
        int c = (int)(i & 127);
        int t = (int)(eg / NE);
        int e = (int)(eg - (long long)t * NE);
        out[i] = __float2bfloat16(
            S_all[t * sS + (long long)idx_all[(long long)t * NE + e] * KC + c]);
    }
}

// ---------- bf16 MMA GEMM w/ cp.async double buffer: C = A@B ----------
#define ASTRIDE 10240  // 128*40*2 bytes
#define BSTRIDE 8704   // 32*136*2 bytes
__global__ __launch_bounds__(256) void bmma_kernel(
    const bf16* __restrict__ A, const bf16* __restrict__ B, float* __restrict__ C,
    int M, int N, int Kp, int do_relu, long long sA, long long sB, long long sC)
{
    A += (long long)blockIdx.z * sA;
    B += (long long)blockIdx.z * sB;
    C += (long long)blockIdx.z * sC;
    __shared__ bf16 As[2][128 * 40];
    __shared__ bf16 Bs[2][32 * 136];
    const int tid = threadIdx.x;
    const int w = tid >> 5, l = tid & 31;
    const int wm = w & 1, wn = w >> 1;
    const int bm = blockIdx.y << 7, bn = blockIdx.x << 7;
    unsigned as0 = (unsigned)__cvta_generic_to_shared(&As[0][0]);
    unsigned bs0 = (unsigned)__cvta_generic_to_shared(&Bs[0][0]);

    float acc[4][4][4];
#pragma unroll
    for (int a = 0; a < 4; a++)
#pragma unroll
        for (int b = 0; b < 4; b++)
#pragma unroll
            for (int c = 0; c < 4; c++) acc[a][b][c] = 0.f;

    unsigned a_addr[4], b_addr[4];
#pragma unroll
    for (int mt = 0; mt < 4; mt++) {
        int row = wm * 64 + mt * 16 + (l & 7) + ((l >> 3) & 1) * 8;
        int col = (l >> 4) << 3;
        a_addr[mt] = as0 + (row * 40 + col) * 2;
    }
#pragma unroll
    for (int nt = 0; nt < 4; nt++) {
        int krow = l & 15;
        int col = wn * 32 + nt * 8;
        b_addr[nt] = bs0 + (krow * 136 + col) * 2;
    }

    const int ar_ = tid >> 2, ag_ = (tid & 3) << 3;   // 512-slot split in 2 iters
    const int niter = Kp >> 5;

#define ISSUE_TILE(it, st) do {                                                   \
    int k0_ = (it) << 5;                                                          \
    _Pragma("unroll")                                                             \
    for (int j_ = 0; j_ < 2; j_++) {                                              \
        int slot_ = tid + j_ * 256;                                               \
        int row_ = slot_ >> 2, grp_ = (slot_ & 3) << 3;                           \
        bool ok_ = (bm + row_) < M;                                               \
        const bf16* src_ = A + (long long)(ok_ ? bm + row_ : 0) * Kp + k0_ + grp_;\
        cp16(as0 + (st) * ASTRIDE + (row_ * 40 + grp_) * 2, src_, ok_);           \
    }                                                                             \
    _Pragma("unroll")                                                             \
    for (int j_ = 0; j_ < 2; j_++) {                                              \
        int slot_ = tid + j_ * 256;                                               \
        int kk_ = slot_ >> 4, grp_ = (slot_ & 15) << 3;                           \
        const bf16* src_ = B + (long long)(k0_ + kk_) * N + bn + grp_;            \
        cp16(bs0 + (st) * BSTRIDE + (kk_ * 136 + grp_) * 2, src_, true);          \
    }                                                                             \
} while (0)

    ISSUE_TILE(0, 0); CP_COMMIT();
    for (int i = 0; i < niter; i++) {
        if (i + 1 < niter) { ISSUE_TILE(i + 1, (i + 1) & 1); CP_COMMIT(); CP_WAIT1(); }
        else CP_WAIT0();
        __syncthreads();
        int st = i & 1;
#pragma unroll
        for (int s = 0; s < 2; s++) {
            unsigned af[4][4], bfr[4][2];
#pragma unroll
            for (int mt = 0; mt < 4; mt++)
                asm volatile("ldmatrix.sync.aligned.m8n8.x4.shared.b16 {%0,%1,%2,%3}, [%4];"
                    : "=r"(af[mt][0]), "=r"(af[mt][1]), "=r"(af[mt][2]), "=r"(af[mt][3])
                    : "r"(a_addr[mt] + st * ASTRIDE + s * 32));
#pragma unroll
            for (int nt = 0; nt < 4; nt++)
                asm volatile("ldmatrix.sync.aligned.m8n8.x2.trans.shared.b16 {%0,%1}, [%2];"
                    : "=r"(bfr[nt][0]), "=r"(bfr[nt][1])
                    : "r"(b_addr[nt] + st * BSTRIDE + s * 4352));
#pragma unroll
            for (int mt = 0; mt < 4; mt++)
#pragma unroll
                for (int nt = 0; nt < 4; nt++)
                    asm volatile(
                        "mma.sync.aligned.m16n8k16.row.col.f32.bf16.bf16.f32 "
                        "{%0,%1,%2,%3}, {%4,%5,%6,%7}, {%8,%9}, {%0,%1,%2,%3};"
                        : "+f"(acc[mt][nt][0]), "+f"(acc[mt][nt][1]),
                          "+f"(acc[mt][nt][2]), "+f"(acc[mt][nt][3])
                        : "r"(af[mt][0]), "r"(af[mt][1]), "r"(af[mt][2]), "r"(af[mt][3]),
                          "r"(bfr[nt][0]), "r"(bfr[nt][1]));
        }
        __syncthreads();
    }
#undef ISSUE_TILE
#pragma unroll
    for (int mt = 0; mt < 4; mt++) {
        int rr = bm + wm * 64 + mt * 16 + (l >> 2);
#pragma unroll
        for (int nt = 0; nt < 4; nt++) {
            int cc = bn + wn * 32 + nt * 8 + ((l & 3) << 1);
            float c0 = acc[mt][nt][0], c1 = acc[mt][nt][1];
            float c2 = acc[mt][nt][2], c3 = acc[mt][nt][3];
            if (do_relu) {
                c0 = fmaxf(c0, 0.f); c1 = fmaxf(c1, 0.f);
                c2 = fmaxf(c2, 0.f); c3 = fmaxf(c3, 0.f);
            }
            if (rr < M) {
                C[(long long)rr * N + cc] = c0;
                C[(long long)rr * N + cc + 1] = c1;
            }
            if (rr + 8 < M) {
                C[(long long)(rr + 8) * N + cc] = c2;
                C[(long long)(rr + 8) * N + cc + 1] = c3;
            }
        }
    }
}

// ---------- split-K MMA, M=128, atomic fp32 epilogue, cp.async pipelined ----------
__global__ __launch_bounds__(256) void bmma_split_kernel(
    const bf16* __restrict__ A, const bf16* __restrict__ B, float* __restrict__ C,
    int N, int Kp, int Kreal, int nsplit, int kchunk,
    long long sA, long long sB, long long sC)
{
    int batch = blockIdx.z / nsplit, split = blockIdx.z - batch * nsplit;
    A += (long long)batch * sA;
    B += (long long)batch * sB;
    C += (long long)batch * sC;
    int kbeg = split * kchunk;
    int kend = min(kbeg + kchunk, Kreal);
    if (kbeg >= kend) return;
    __shared__ bf16 As[2][128 * 40];
    __shared__ bf16 Bs[2][32 * 136];
    const int tid = threadIdx.x;
    const int w = tid >> 5, l = tid & 31;
    const int wm = w & 1, wn = w >> 1;
    const int bn = blockIdx.x << 7;
    unsigned as0 = (unsigned)__cvta_generic_to_shared(&As[0][0]);
    unsigned bs0 = (unsigned)__cvta_generic_to_shared(&Bs[0][0]);

    float acc[4][4][4];
#pragma unroll
    for (int a = 0; a < 4; a++)
#pragma unroll
        for (int b = 0; b < 4; b++)
#pragma unroll
            for (int c = 0; c < 4; c++) acc[a][b][c] = 0.f;

    unsigned a_addr[4], b_addr[4];
#pragma unroll
    for (int mt = 0; mt < 4; mt++) {
        int row = wm * 64 + mt * 16 + (l & 7) + ((l >> 3) & 1) * 8;
        int col = (l >> 4) << 3;
        a_addr[mt] = as0 + (row * 40 + col) * 2;
    }
#pragma unroll
    for (int nt = 0; nt < 4; nt++) {
        int krow = l & 15;
        int col = wn * 32 + nt * 8;
        b_addr[nt] = bs0 + (krow * 136 + col) * 2;
    }
    const int niter = (kend - kbeg + 31) >> 5;

#define ISSUE_TILE(it, st) do {                                                   \
    int k0_ = kbeg + ((it) << 5);                                                 \
    _Pragma("unroll")                                                             \
    for (int j_ = 0; j_ < 2; j_++) {                                              \
        int slot_ = tid + j_ * 256;                                               \
        int row_ = slot_ >> 2, grp_ = (slot_ & 3) << 3;                           \
        bool ok_ = (k0_ + grp_ + 8) <= Kreal;                                     \
        const bf16* src_ = A + (long long)row_ * Kp + (ok_ ? k0_ + grp_ : 0);     \
        cp16(as0 + (st) * ASTRIDE + (row_ * 40 + grp_) * 2, src_, ok_);           \
    }                                                                             \
    _Pragma("unroll")                                                             \
    for (int j_ = 0; j_ < 2; j_++) {                                              \
        int slot_ = tid + j_ * 256;                                               \
        int kk_ = slot_ >> 4, grp_ = (slot_ & 15) << 3;                           \
        bool ok_ = (k0_ + kk_) < Kreal;                                           \
        const bf16* src_ = B + (long long)(ok_ ? k0_ + kk_ : 0) * N + bn + grp_;  \
        cp16(bs0 + (st) * BSTRIDE + (kk_ * 136 + grp_) * 2, src_, ok_);           \
    }                                                                             \
} while (0)

    ISSUE_TILE(0, 0); CP_COMMIT();
    for (int i = 0; i < niter; i++) {
        if (i + 1 < niter) { ISSUE_TILE(i + 1, (i + 1) & 1); CP_COMMIT(); CP_WAIT1(); }
        else CP_WAIT0();
        __syncthreads();
        int st = i & 1;
#pragma unroll
        for (int s = 0; s < 2; s++) {
            unsigned af[4][4], bfr[4][2];
#pragma unroll
            for (int mt = 0; mt < 4; mt++)
                asm volatile("ldmatrix.sync.aligned.m8n8.x4.shared.b16 {%0,%1,%2,%3}, [%4];"
                    : "=r"(af[mt][0]), "=r"(af[mt][1]), "=r"(af[mt][2]), "=r"(af[mt][3])
                    : "r"(a_addr[mt] + st * ASTRIDE + s * 32));
#pragma unroll
            for (int nt = 0; nt < 4; nt++)
                asm volatile("ldmatrix.sync.aligned.m8n8.x2.trans.shared.b16 {%0,%1}, [%2];"
                    : "=r"(bfr[nt][0]), "=r"(bfr[nt][1])
                    : "r"(b_addr[nt] + st * BSTRIDE + s * 4352));
#pragma unroll
            for (int mt = 0; mt < 4; mt++)
#pragma unroll
                for (int nt = 0; nt < 4; nt++)
                    asm volatile(
                        "mma.sync.aligned.m16n8k16.row.col.f32.bf16.bf16.f32 "
                        "{%0,%1,%2,%3}, {%4,%5,%6,%7}, {%8,%9}, {%0,%1,%2,%3};"
                        : "+f"(acc[mt][nt][0]), "+f"(acc[mt][nt][1]),
                          "+f"(acc[mt][nt][2]), "+f"(acc[mt][nt][3])
                        : "r"(af[mt][0]), "r"(af[mt][1]), "r"(af[mt][2]), "r"(af[mt][3]),
                          "r"(bfr[nt][0]), "r"(bfr[nt][1]));
        }
        __syncthreads();
    }
#undef ISSUE_TILE
#pragma unroll
    for (int mt = 0; mt < 4; mt++) {
        int rr = wm * 64 + mt * 16 + (l >> 2);
#pragma unroll
        for (int nt = 0; nt < 4; nt++) {
            int cc = bn + wn * 32 + nt * 8 + ((l & 3) << 1);
            atomicAdd(&C[(long long)rr * N + cc],     acc[mt][nt][0]);
            atomicAdd(&C[(long long)rr * N + cc + 1], acc[mt][nt][1]);
            atomicAdd(&C[(long long)(rr + 8) * N + cc],     acc[mt][nt][2]);
            atomicAdd(&C[(long long)(rr + 8) * N + cc + 1], acc[mt][nt][3]);
        }
    }
}

// ---------- fp32 SGEMM (conv2 only) ----------
__global__ __launch_bounds__(256) void sgemm_kernel(
    const float* __restrict__ A, const float* __restrict__ B, float* __restrict__ C,
    int M, int N, int Kd, long long sA, long long sB, long long sC)
{
    A += (long long)blockIdx.z * sA; B += (long long)blockIdx.z * sB;
    C += (long long)blockIdx.z * sC;
    __shared__ float As[16][68], Bs[16][68];
    const int tid = threadIdx.x, tx = tid & 15, ty = tid >> 4;
    const int bm = blockIdx.y << 6, bn = blockIdx.x << 6;
    const int arow = tid >> 2, acol = (tid & 3) << 2;
    const int brow = tid >> 4, bcol = (tid & 15) << 2;
    float acc[4][4];
#pragma unroll
    for (int i = 0; i < 4; i++)
#pragma unroll
        for (int j = 0; j < 4; j++) acc[i][j] = 0.f;
    const int gr = bm + arow;
    for (int k0 = 0; k0 < Kd; k0 += 16) {
        float4 av = make_float4(0.f, 0.f, 0.f, 0.f);
        if (gr < M) av = *(const float4*)(A + (long long)gr * Kd + k0 + acol);
        As[acol][arow] = av.x; As[acol + 1][arow] = av.y;
        As[acol + 2][arow] = av.z; As[acol + 3][arow] = av.w;
        *(float4*)&Bs[brow][bcol] = *(const float4*)(B + (long long)(k0 + brow) * N + bn + bcol);
        __syncthreads();
#pragma unroll
        for (int k = 0; k < 16; k++) {
            float4 a4 = *(const float4*)&As[k][ty << 2];
            float4 b4 = *(const float4*)&Bs[k][tx << 2];
            float ar[4] = {a4.x, a4.y, a4.z, a4.w};
            float br_[4] = {b4.x, b4.y, b4.z, b4.w};
#pragma unroll
            for (int i = 0; i < 4; i++)
#pragma unroll
                for (int j = 0; j < 4; j++) acc[i][j] = fmaf(ar[i], br_[j], acc[i][j]);
        }
        __syncthreads();
    }
#pragma unroll
    for (int i = 0; i < 4; i++) {
        int r = bm + (ty << 2) + i;
        if (r >= M) continue;
        *(float4*)(C + (long long)r * N + bn + (tx << 2)) =
            make_float4(acc[i][0], acc[i][1], acc[i][2], acc[i][3]);
    }
}

// softmax width-128 rows + entropy + fused B-triplet emit
__global__ void softmax_ent_kernel(float* __restrict__ S, int N, float inv_n,
                                   float* __restrict__ ent_acc, bf16* __restrict__ outB)
{
    int g = blockIdx.x * blockDim.x + threadIdx.x;
    int w = g >> 5, lane = g & 31;
    if (w >= N) return;
    float* row = S + (long long)w * KC;
    float v0 = row[lane], v1 = row[lane + 32], v2 = row[lane + 64], v3 = row[lane + 96];
    float m = fmaxf(fmaxf(v0, v1), fmaxf(v2, v3));
    for (int o = 16; o; o >>= 1) m = fmaxf(m, __shfl_xor_sync(~0u, m, o));
    v0 = expf(v0 - m); v1 = expf(v1 - m); v2 = expf(v2 - m); v3 = expf(v3 - m);
    float s = v0 + v1 + v2 + v3;
    for (int o = 16; o; o >>= 1) s += __shfl_xor_sync(~0u, s, o);
    float inv = 1.f / s;
    v0 *= inv; v1 *= inv; v2 *= inv; v3 *= inv;
    row[lane] = v0; row[lane + 32] = v1; row[lane + 64] = v2; row[lane + 96] = v3;
    bf16* b0 = outB + (long long)(3 * w) * KC;
    float vv[4] = {v0, v1, v2, v3};
#pragma unroll
    for (int q = 0; q < 4; q++) {
        int c = lane + q * 32;
        bf16 h = __float2bfloat16(vv[q]);
        bf16 lo = __float2bfloat16(vv[q] - __bfloat162float(h));
        b0[c] = h; b0[KC + c] = lo; b0[2 * KC + c] = h;
    }
    float e = -(v0 * logf(v0 + 1e-15f) + v1 * logf(v1 + 1e-15f)
              + v2 * logf(v2 + 1e-15f) + v3 * logf(v3 + 1e-15f));
    for (int o = 16; o; o >>= 1) e += __shfl_xor_sync(~0u, e, o);
    if (lane == 0) atomicAdd(ent_acc, e * inv_n);
}

// ---------- batched edge kernels ----------
__global__ __launch_bounds__(256) void edge_score_kernel(
    const float* __restrict__ l_all, const float* __restrict__ r_all,
    const int* __restrict__ src_all, const int* __restrict__ tgt_all,
    const float* __restrict__ a1_all, float* __restrict__ esc_all,
    float* __restrict__ emax_all)
{
    int t = blockIdx.x / EB;
    const float* l = l_all + (long long)t * NPKG * FD;
    const float* r = r_all + (long long)t * NTGTN * FD;
    const int* src = src_all + (long long)t * NE;
    const int* tgt = tgt_all + (long long)t * NE;
    float* esc = esc_all + (long long)t * NE * 4;
    float* emax = emax_all + (long long)t * NTGTN * 4;
    __shared__ float a_s[256];
    int tid = threadIdx.x;
    a_s[tid] = a1_all[t * 256 + tid];
    __syncthreads();
    int e = (((blockIdx.x - t * EB) * 256) + tid) >> 5;
    int lane = tid & 31;
    int tg = tgt[e];
    const float* lr = l + (long long)src[e] * FD;
    const float* rr = r + (long long)tg * FD;
#pragma unroll
    for (int h = 0; h < 4; h++) {
        float acc = 0.f;
#pragma unroll
        for (int q = 0; q < 2; q++) {
            int c = h * 64 + lane + q * 32;
            float v = lr[c] + rr[c];
            v = v > 0.f ? v : 0.2f * v;
            acc = fmaf(v, a_s[c], acc);
        }
        for (int o = 16; o; o >>= 1) acc += __shfl_xor_sync(~0u, acc, o);
        if (lane == 0) { esc[e * 4 + h] = acc; atomicMaxFloat(&emax[tg * 4 + h], acc); }
    }
}

__global__ void edge_exp_kernel(const int* __restrict__ tgt_all, float* __restrict__ esc_all,
                                const float* __restrict__ emax_all, float* __restrict__ eden_all)
{
    long long idx = blockIdx.x * (long long)blockDim.x + threadIdx.x;
    if (idx >= (long long)NTY * NE * 4) return;
    int t = (int)(idx / ((long long)NE * 4));
    long long rem = idx - (long long)t * NE * 4;
    int e = (int)(rem >> 2), h = (int)(rem & 3);
    int tg = tgt_all[(long long)t * NE + e];
    float m = emax_all[(long long)t * NTGTN * 4 + tg * 4 + h];
    if (!isfinite(m)) m = 0.f;
    float ex = expf(esc_all[idx] - m);
    esc_all[idx] = ex;
    atomicAdd(&eden_all[(long long)t * NTGTN * 4 + tg * 4 + h], ex);
}

__global__ __launch_bounds__(256) void edge_aggr_kernel(
    const float* __restrict__ l_all, const int* __restrict__ src_all,
    const int* __restrict__ tgt_all, const float* __restrict__ esc_all,
    const float* __restrict__ eden_all, float* __restrict__ htgt_all)
{
    int t = blockIdx.x / EB;
    const float* l = l_all + (long long)t * NPKG * FD;
    const int* src = src_all + (long long)t * NE;
    const int* tgt = tgt_all + (long long)t * NE;
    const float* esc = esc_all + (long long)t * NE * 4;
    const float* eden = eden_all + (long long)t * NTGTN * 4;
    float* outh = htgt_all + (long long)t * NTGTN * FD;
    int tid = threadIdx.x;
    int e = (((blockIdx.x - t * EB) * 256) + tid) >> 5;
    int lane = tid & 31;
    int s = src[e], tg = tgt[e];
    float alpha[4];
#pragma unroll
    for (int h = 0; h < 4; h++)
        alpha[h] = esc[e * 4 + h] / (eden[tg * 4 + h] + 1e-16f);
    const float* lr = l + (long long)s * FD;
    float* orow = outh + (long long)tg * FD;
#pragma unroll
    for (int q = 0; q < 8; q++) {
        int c = lane + q * 32;
        atomicAdd(&orow[c], lr[c] * alpha[c >> 6]);
    }
}

__global__ void mulsum_kernel(const float* __restrict__ a, const float* __restrict__ b_all,
                              int n, float* __restrict__ slots)
{
    const float* b = b_all + (long long)blockIdx.y * n;
    __shared__ float sred[8];
    float acc = 0.f;
    for (int i = blockIdx.x * blockDim.x + threadIdx.x; i < n; i += gridDim.x * blockDim.x)
        acc += a[i] * b[i];
    for (int o = 16; o; o >>= 1) acc += __shfl_xor_sync(~0u, acc, o);
    if ((threadIdx.x & 31) == 0) sred[threadIdx.x >> 5] = acc;
    __syncthreads();
    if (threadIdx.x == 0) {
        float t = 0.f;
        for (int i = 0; i < 8; i++) t += sred[i];
        atomicAdd(&slots[blockIdx.y], t);
    }
}

__global__ void link_kernel(const float* __restrict__ Apool_all, float* __restrict__ scal) {
    __shared__ float red[4];
    int tid = threadIdx.x;
    float link = 0.f;
    for (int t = 0; t < NTY; t++) {
        float d = Apool_all[t * KC * KC + tid * (KC + 1)];
        for (int o = 16; o; o >>= 1) d += __shfl_xor_sync(~0u, d, o);
        if ((tid & 31) == 0) red[tid >> 5] = d;
        __syncthreads();
        if (tid == 0) {
            float dot = red[0] + red[1] + red[2] + red[3];
            float n2 = fmaxf((float)NE - 2.f * dot + scal[16 + t], 0.f) + 1e-12f;
            link += sqrtf(n2) * (1.f / ((float)NPKG * (float)NTGTN));
        }
        __syncthreads();
    }
    if (tid == 0) scal[1] = link;
}

__global__ __launch_bounds__(256) void attn2_score_kernel(
    const float* __restrict__ l2, const float* __restrict__ r2,
    const float* __restrict__ Apool, const float* __restrict__ a2, float* __restrict__ e2)
{
    int g = blockIdx.x * blockDim.x + threadIdx.x;
    int w = g >> 5, lane = g & 31;
    if (w >= NTY * KC * KC) return;
    int t = w >> 14, rem = w & 16383, i = rem >> 7, j = rem & 127;
    const float* li = l2 + ((long long)t * KC + i) * FD;
    const float* rj = r2 + ((long long)t * KC + j) * FD;
    const float* av = a2 + t * 256;
    float ap = Apool[(long long)t * KC * KC + i * KC + j];
#pragma unroll
    for (int h = 0; h < 4; h++) {
        float acc = 0.f;
#pragma unroll
        for (int q = 0; q < 2; q++) {
            int c = h * 64 + lane + q * 32;
            float v = li[c] + rj[c];
            v = v > 0.f ? v : 0.2f * v;
            acc = fmaf(v, av[c], acc);
        }
        for (int o = 16; o; o >>= 1) acc += __shfl_xor_sync(~0u, acc, o);
        if (lane == 0) e2[(long long)w * 4 + h] = (ap > 0.f) ? acc : -1e9f;
    }
}

__global__ __launch_bounds__(128) void attn2_softmax_kernel(
    const float* __restrict__ e2, float* __restrict__ out_attn)
{
    int j = blockIdx.x, t = blockIdx.y, i = threadIdx.x;
    int lane = i & 31, wid = i >> 5;
    __shared__ float wred[4][4];
    long long base = (((long long)t * KC + i) * KC + j) * 4;
    float e[4], m[4], ex[4];
#pragma unroll
    for (int h = 0; h < 4; h++) e[h] = e2[base + h];
#pragma unroll
    for (int h = 0; h < 4; h++) {
        float x = e[h];
        for (int o = 16; o; o >>= 1) x = fmaxf(x, __shfl_xor_sync(~0u, x, o));
        if (lane == 0) wred[wid][h] = x;
    }
    __syncthreads();
#pragma unroll
    for (int h = 0; h < 4; h++)
        m[h] = fmaxf(fmaxf(wred[0][h], wred[1][h]), fmaxf(wred[2][h], wred[3][h]));
    __syncthreads();
#pragma unroll
    for (int h = 0; h < 4; h++) {
        ex[h] = expf(e[h] - m[h]);
        float x = ex[h];
        for (int o = 16; o; o >>= 1) x += __shfl_xor_sync(~0u, x, o);
        if (lane == 0) wred[wid][h] = x;
    }
    __syncthreads();
#pragma unroll
    for (int h = 0; h < 4; h++) {
        float sm = wred[0][h] + wred[1][h] + wred[2][h] + wred[3][h];
        out_attn[base + h] = ex[h] / sm;
    }
}

__global__ void cls_kernel(const float* __restrict__ pool, const float* __restrict__ Wcls,
                           const float* __restrict__ bcls, float* __restrict__ out)
{
    int g = blockIdx.x * blockDim.x + threadIdx.x;
    int w = g >> 5, lane = g & 31;
    if (w >= (NTY + 1) * KC) return;
    const float* row = pool + (long long)w * FD;
    float acc = 0.f;
#pragma unroll
    for (int q = 0; q < 8; q++) acc += row[lane + q * 32] * Wcls[lane + q * 32];
    for (int o = 16; o; o >>= 1) acc += __shfl_xor_sync(~0u, acc, o);
    if (lane == 0) out[w] = 1.f / (1.f + expf(-(acc + bcls[0])));
}

__global__ void finalize_kernel(const float* __restrict__ scal, float* __restrict__ out) {
    out[(NTY + 1) * KC] = scal[0] + scal[1];
}

extern "C" void kernel_launch(void* const* d_in, const int* in_sizes, int n_in,
                              void* d_out, int out_size)
{
    (void)in_sizes; (void)n_in; (void)out_size;
    const float* x_pkg   = (const float*)d_in[0];
    const float* x_tgt   = (const float*)d_in[1];
    const int*   src_idx = (const int*)d_in[2];
    const int*   tgt_idx = (const int*)d_in[3];
    const float* W1s     = (const float*)d_in[4];
    const float* W1t     = (const float*)d_in[5];
    const float* a1      = (const float*)d_in[6];
    const float* Wpkg    = (const float*)d_in[7];
    const float* Wassign = (const float*)d_in[8];
    const float* W2s     = (const float*)d_in[9];
    const float* W2t     = (const float*)d_in[10];
    const float* a2      = (const float*)d_in[11];
    const float* Wcls    = (const float*)d_in[12];
    const float* bcls    = (const float*)d_in[13];
    float* out = (float*)d_out;

    void* ap = nullptr;
    cudaGetSymbolAddress(&ap, g_arena);
    char* AR = (char*)ap;
    float* l_all  = (float*)(AR + O_LALL);
    float* r_all  = (float*)(AR + O_RALL);
    bf16*  GsT    = (bf16*)(AR + O_GST);
    bf16*  Gt     = (bf16*)(AR + O_GT);
    float* hpkg   = (float*)(AR + O_HPKG);
    float* htgt   = (float*)(AR + O_HTGT);
    float* Spkg   = (float*)(AR + O_SPKG);
    float* Stgt   = (float*)(AR + O_STGT);
    float* pool   = (float*)(AR + O_POOL);
    float* Mpkg   = (float*)(AR + O_MPKG);
    float* Mt     = (float*)(AR + O_MT);
    float* Apool  = (float*)(AR + O_APOOL);
    float* l2     = (float*)(AR + O_L2);
    float* r2     = (float*)(AR + O_R2);
    float* esc    = (float*)(AR + O_ESC);
    float* emax   = (float*)(AR + O_EMAX);
    float* eden   = (float*)(AR + O_EDEN);
    float* scal   = (float*)(AR + O_SCAL);
    bf16* xpkg3   = (bf16*)(AR + O_XPKG3);
    bf16* xtgt3   = (bf16*)(AR + O_XTGT3);
    bf16* htgtB   = (bf16*)(AR + O_HTGTB);
    bf16* W1s3    = (bf16*)(AR + O_W1S3);
    bf16* W1t3    = (bf16*)(AR + O_W1T3);
    bf16* Wpkg3   = (bf16*)(AR + O_WPKG3);
    bf16* hpkg3   = (bf16*)(AR + O_HPKG3);
    bf16* htgt3   = (bf16*)(AR + O_HTGT3);
    bf16* Was3    = (bf16*)(AR + O_WAS3);
    bf16* STpA    = (bf16*)(AR + O_STPA);
    bf16* SpB     = (bf16*)(AR + O_SPB);
    bf16* hpkgB   = (bf16*)(AR + O_HPKGB);
    bf16* STtA    = (bf16*)(AR + O_STTA);
    bf16* StgB    = (bf16*)(AR + O_STGB);

    fill_kernel<<<1, 64>>>(scal, 0.f, 32);
    fill_kernel<<<512, 256>>>(pool, 0.f, 7LL * KC * FD);
    fill_kernel<<<256, 256>>>(Mpkg, 0.f, (long long)(16384 + 6 * 16384 + 6 * 16384));
    fill_kernel<<<512, 256>>>(emax, -INFINITY, (long long)NTY * NTGTN * 4);
    fill_kernel<<<512, 256>>>(eden, 0.f, (long long)NTY * NTGTN * 4);
    fill_kernel<<<4096, 256>>>(htgt, 0.f, (long long)NTY * NTGTN * FD);

    // input conversions
    cvtA_kernel<<<2048, 256>>>(x_pkg, xpkg3, FIN, KP1, (long long)NPKG * FIN);
    padA_kernel<<<256, 256>>>(xpkg3, NPKG, 3 * FIN, KP1);
    cvtA_kernel<<<4096, 256>>>(x_tgt, xtgt3, FIN, KP1, (long long)NTY * NTGTN * FIN);
    padA_kernel<<<512, 256>>>(xtgt3, (long long)NTY * NTGTN, 3 * FIN, KP1);
    cvtB_kernel<<<1024, 256>>>(W1s, W1s3, FIN, FD, KP1, (long long)NTY * FIN * FD);
    padB_kernel<<<64, 256>>>(W1s3, NTY, 3 * FIN, KP1, FD);
    cvtB_kernel<<<1024, 256>>>(W1t, W1t3, FIN, FD, KP1, (long long)NTY * FIN * FD);
    padB_kernel<<<64, 256>>>(W1t3, NTY, 3 * FIN, KP1, FD);
    cvtB_kernel<<<256, 256>>>(Wpkg, Wpkg3, FIN, FD, KP1, (long long)FIN * FD);
    padB_kernel<<<16, 256>>>(Wpkg3, 1, 3 * FIN, KP1, FD);
    cvtB_kernel<<<512, 256>>>(Wassign, Was3, FD, KC, KP2, (long long)(NTY + 1) * FD * KC);

    // conv1 projections
    bmma_kernel<<<dim3(FD / 128, (NPKG + 127) / 128, NTY), 256>>>(
        xpkg3, W1s3, l_all, NPKG, FD, KP1, 0,
        0LL, (long long)KP1 * FD, (long long)NPKG * FD);
    bmma_kernel<<<dim3(FD / 128, (NTGTN + 127) / 128, NTY), 256>>>(
        xtgt3, W1t3, r_all, NTGTN, FD, KP1, 0,
        (long long)NTGTN * KP1, (long long)KP1 * FD, (long long)NTGTN * FD);
    bmma_kernel<<<dim3(FD / 128, (NPKG + 127) / 128), 256>>>(
        xpkg3, Wpkg3, hpkg, NPKG, FD, KP1, 1, 0, 0, 0);

    // pkg assignment + softmax (+SpB emit)
    relu_cvt_kernel<<<2048, 256>>>(hpkg, hpkg3, hpkgB, (long long)NPKG * FD);
    bmma_kernel<<<dim3(1, (NPKG + 127) / 128), 256>>>(
        hpkg3, Was3, Spkg, NPKG, KC, KP2, 0, 0, 0, 0);
    softmax_ent_kernel<<<(NPKG + 7) / 8, 256>>>(Spkg, NPKG, 1.0f / NPKG, scal, SpB);

    // pkg pooled + Mpkg
    cvtT_kernel<<<dim3(625, 4, 1), 256>>>(Spkg, STpA, NPKG, KC, 0, 0);
    bmma_split_kernel<<<dim3(2, 1, 15), 256>>>(
        STpA, hpkgB, pool, FD, 3 * NPKG, 3 * NPKG, 15, 4096, 0, 0, 0);
    bmma_split_kernel<<<dim3(1, 1, 15), 256>>>(
        STpA, SpB, Mpkg, KC, 3 * NPKG, 3 * NPKG, 15, 4096, 0, 0, 0);

    // edge phase
    edge_score_kernel<<<NTY * EB, 256>>>(l_all, r_all, src_idx, tgt_idx, a1, esc, emax);
    edge_exp_kernel<<<(NTY * NE * 4 + 255) / 256, 256>>>(tgt_idx, esc, emax, eden);
    edge_aggr_kernel<<<NTY * EB, 256>>>(l_all, src_idx, tgt_idx, esc, eden, htgt);

    // tgt: fused relu+cvt, assignment, softmax(+StgB)
    relu_cvt_kernel<<<4096, 256>>>(htgt, htgt3, htgtB, (long long)NTY * NTGTN * FD);
    bmma_kernel<<<dim3(1, (NTGTN + 127) / 128, NTY), 256>>>(
        htgt3, Was3 + (long long)KP2 * KC, Stgt, NTGTN, KC, KP2,
        0, (long long)NTGTN * KP2, (long long)KP2 * KC, (long long)NTGTN * KC);
    softmax_ent_kernel<<<(NTY * NTGTN + 7) / 8, 256>>>(Stgt, NTY * NTGTN, 1.0f / NTGTN,
                                                        scal, StgB);

    // tgt pooled + Mt
    cvtT_kernel<<<dim3(938, 4, NTY), 256>>>(Stgt, STtA, NTGTN, KC,
        (long long)NTGTN * KC, (long long)KC * 3 * NTGTN);
    bmma_split_kernel<<<dim3(2, 1, NTY * 22), 256>>>(
        STtA, htgtB, pool + (long long)KC * FD, FD, 3 * NTGTN, 3 * NTGTN, 22, 4096,
        (long long)KC * 3 * NTGTN, (long long)3 * NTGTN * FD, (long long)KC * FD);
    bmma_split_kernel<<<dim3(1, 1, NTY * 22), 256>>>(
        STtA, StgB, Mt, KC, 3 * NTGTN, 3 * NTGTN, 22, 4096,
        (long long)KC * 3 * NTGTN, (long long)3 * NTGTN * KC, (long long)KC * KC);

    // A_pool (plain bf16 gathers)
    gatherT_kernel<<<dim3(NE / 32, KC / 32, NTY), 256>>>(Spkg, src_idx, GsT);
    gatherB_kernel<<<4096, 256>>>(Stgt, tgt_idx, Gt, (long long)NTGTN * KC);
    bmma_split_kernel<<<dim3(1, 1, NTY * 8), 256>>>(
        GsT, Gt, Apool, KC, NE, NE, 8, 12544,
        (long long)KC * NE, (long long)NE * KC, (long long)KC * KC);

    // link loss
    mulsum_kernel<<<dim3(8, NTY), 256>>>(Mpkg, Mt, KC * KC, scal + 16);
    link_kernel<<<1, 128>>>(Apool, scal);

    // conv2 + attention + classifier
    sgemm_kernel<<<dim3(FD / 64, KC / 64, NTY), 256>>>(
        pool, W2s, l2, KC, FD, FD, 0, (long long)FD * FD, (long long)KC * FD);
    sgemm_kernel<<<dim3(FD / 64, KC / 64, NTY), 256>>>(
        pool + (long long)KC * FD, W2t, r2, KC, FD, FD,
        (long long)KC * FD, (long long)FD * FD, (long long)KC * FD);

    attn2_score_kernel<<<NTY * KC * KC * 32 / 256, 256>>>(l2, r2, Apool, a2, esc);
    attn2_softmax_kernel<<<dim3(KC, NTY), 128>>>(esc, out + (NTY + 1) * KC + 1);

    cls_kernel<<<(NTY + 1) * KC * 32 / 256, 256>>>(pool, Wcls, bcls, out);
    finalize_kernel<<<1, 1>>>(scal, out);
}